// round 4
// baseline (speedup 1.0000x reference)
#include <cuda_runtime.h>
#include <math.h>

// B=4, C=256, H=W=32, NH=8, HC=32, G=4, GC=64, ns=1024, KK=5, ORF=2
typedef unsigned long long u64;

__device__ __forceinline__ u64 fma2(u64 a, u64 b, u64 c) {
    u64 d;
    asm("fma.rn.f32x2 %0, %1, %2, %3;" : "=l"(d) : "l"(a), "l"(b), "l"(c));
    return d;
}
__device__ __forceinline__ u64 pack2(float lo, float hi) {
    u64 r;
    asm("mov.b64 %0, {%1, %2};" : "=l"(r) : "f"(lo), "f"(hi));
    return r;
}
__device__ __forceinline__ u64 dup2(float x) { return pack2(x, x); }
__device__ __forceinline__ void unpack2(u64 a, float& lo, float& hi) {
    asm("mov.b64 {%0, %1}, %2;" : "=f"(lo), "=f"(hi) : "l"(a));
}

// ---------------- scratch ----------------
__device__ float g_q [4 * 256 * 1024];
__device__ float g_xs[4 * 256 * 1024];
__device__ float g_k [4 * 256 * 1024];
__device__ float g_v [4 * 256 * 1024];
__device__ float g_o [4 * 256 * 1024];
__device__ float g_pos[16 * 1024 * 2];

// ---------------- SGEMM (single weight): 128x64 tile, FFMA2 over m-pairs ----
__global__ __launch_bounds__(256)
void gemm_conv(const float* __restrict__ Wm, const float* __restrict__ X,
               const float* __restrict__ bias, float* __restrict__ Y)
{
    const int b  = blockIdx.z;
    const int m0 = blockIdx.y * 128;
    const int n0 = blockIdx.x * 64;
    const float* Xb = X + b * 262144;
    float* Yb = Y + b * 262144;

    __shared__ float As[16][132];
    __shared__ float Bs[16][64];

    const int tid = threadIdx.x;
    const int tx = tid & 15;
    const int ty = tid >> 4;

    const int am = tid >> 1;
    const int ak = (tid & 1) * 8;
    const int bn = tid & 63;
    const int bk = (tid >> 6) * 4;

    u64 acc2[4][4];
#pragma unroll
    for (int p = 0; p < 4; p++)
#pragma unroll
        for (int j = 0; j < 4; j++) acc2[p][j] = 0ULL;

    float4 wa, wb;
    float  xr[4];
    {
        const float* wp = &Wm[(m0 + am) * 256 + ak];
        wa = *(const float4*)wp;
        wb = *(const float4*)(wp + 4);
#pragma unroll
        for (int u = 0; u < 4; u++) xr[u] = Xb[(bk + u) * 1024 + n0 + bn];
    }

    for (int k0 = 0; k0 < 256; k0 += 16) {
        As[ak + 0][am] = wa.x; As[ak + 1][am] = wa.y;
        As[ak + 2][am] = wa.z; As[ak + 3][am] = wa.w;
        As[ak + 4][am] = wb.x; As[ak + 5][am] = wb.y;
        As[ak + 6][am] = wb.z; As[ak + 7][am] = wb.w;
#pragma unroll
        for (int u = 0; u < 4; u++) Bs[bk + u][bn] = xr[u];
        __syncthreads();

        if (k0 + 16 < 256) {
            const float* wp = &Wm[(m0 + am) * 256 + k0 + 16 + ak];
            wa = *(const float4*)wp;
            wb = *(const float4*)(wp + 4);
#pragma unroll
            for (int u = 0; u < 4; u++)
                xr[u] = Xb[(k0 + 16 + bk + u) * 1024 + n0 + bn];
        }

#pragma unroll
        for (int kk = 0; kk < 16; kk++) {
            const u64* a2 = (const u64*)&As[kk][ty * 8];
            float4 b4 = *(const float4*)&Bs[kk][tx * 4];
            u64 bd[4] = {dup2(b4.x), dup2(b4.y), dup2(b4.z), dup2(b4.w)};
#pragma unroll
            for (int p = 0; p < 4; p++) {
                u64 av = a2[p];
#pragma unroll
                for (int j = 0; j < 4; j++)
                    acc2[p][j] = fma2(av, bd[j], acc2[p][j]);
            }
        }
        __syncthreads();
    }

#pragma unroll
    for (int p = 0; p < 4; p++) {
        float lo[4], hi[4];
#pragma unroll
        for (int j = 0; j < 4; j++) unpack2(acc2[p][j], lo[j], hi[j]);
        int r0 = m0 + ty * 8 + 2 * p;
        float b0 = bias[r0], b1 = bias[r0 + 1];
        float4 o0 = make_float4(lo[0] + b0, lo[1] + b0, lo[2] + b0, lo[3] + b0);
        float4 o1 = make_float4(hi[0] + b1, hi[1] + b1, hi[2] + b1, hi[3] + b1);
        *(float4*)&Yb[r0 * 1024 + n0 + tx * 4]       = o0;
        *(float4*)&Yb[(r0 + 1) * 1024 + n0 + tx * 4] = o1;
    }
}

// ---------------- merged K+V GEMM: one wave (128 blocks), X tile loaded once
__global__ __launch_bounds__(256)
void gemm_kv(const float* __restrict__ Wk, const float* __restrict__ bk_,
             float* __restrict__ Yk,
             const float* __restrict__ Wv, const float* __restrict__ bv_,
             float* __restrict__ Yv, const float* __restrict__ X)
{
    const int b  = blockIdx.z;
    const int m0 = blockIdx.y * 128;
    const int n0 = blockIdx.x * 64;
    const float* Xb = X + b * 262144;

    __shared__ float As[2][16][132];
    __shared__ float Bs[16][64];

    const int tid = threadIdx.x;
    const int tx = tid & 15;
    const int ty = tid >> 4;

    const int am = tid >> 1;
    const int ak = (tid & 1) * 8;
    const int bn = tid & 63;
    const int bk = (tid >> 6) * 4;

    u64 acc2[2][4][4];
#pragma unroll
    for (int s = 0; s < 2; s++)
#pragma unroll
        for (int p = 0; p < 4; p++)
#pragma unroll
            for (int j = 0; j < 4; j++) acc2[s][p][j] = 0ULL;

    float4 wka, wkb, wva, wvb;
    float  xr[4];
    {
        const float* wp = &Wk[(m0 + am) * 256 + ak];
        wka = *(const float4*)wp;  wkb = *(const float4*)(wp + 4);
        const float* vp = &Wv[(m0 + am) * 256 + ak];
        wva = *(const float4*)vp;  wvb = *(const float4*)(vp + 4);
#pragma unroll
        for (int u = 0; u < 4; u++) xr[u] = Xb[(bk + u) * 1024 + n0 + bn];
    }

    for (int k0 = 0; k0 < 256; k0 += 16) {
        As[0][ak + 0][am] = wka.x; As[0][ak + 1][am] = wka.y;
        As[0][ak + 2][am] = wka.z; As[0][ak + 3][am] = wka.w;
        As[0][ak + 4][am] = wkb.x; As[0][ak + 5][am] = wkb.y;
        As[0][ak + 6][am] = wkb.z; As[0][ak + 7][am] = wkb.w;
        As[1][ak + 0][am] = wva.x; As[1][ak + 1][am] = wva.y;
        As[1][ak + 2][am] = wva.z; As[1][ak + 3][am] = wva.w;
        As[1][ak + 4][am] = wvb.x; As[1][ak + 5][am] = wvb.y;
        As[1][ak + 6][am] = wvb.z; As[1][ak + 7][am] = wvb.w;
#pragma unroll
        for (int u = 0; u < 4; u++) Bs[bk + u][bn] = xr[u];
        __syncthreads();

        if (k0 + 16 < 256) {
            const float* wp = &Wk[(m0 + am) * 256 + k0 + 16 + ak];
            wka = *(const float4*)wp;  wkb = *(const float4*)(wp + 4);
            const float* vp = &Wv[(m0 + am) * 256 + k0 + 16 + ak];
            wva = *(const float4*)vp;  wvb = *(const float4*)(vp + 4);
#pragma unroll
            for (int u = 0; u < 4; u++)
                xr[u] = Xb[(k0 + 16 + bk + u) * 1024 + n0 + bn];
        }

#pragma unroll
        for (int kk = 0; kk < 16; kk++) {
            float4 b4 = *(const float4*)&Bs[kk][tx * 4];
            u64 bd[4] = {dup2(b4.x), dup2(b4.y), dup2(b4.z), dup2(b4.w)};
#pragma unroll
            for (int s = 0; s < 2; s++) {
                const u64* a2 = (const u64*)&As[s][kk][ty * 8];
#pragma unroll
                for (int p = 0; p < 4; p++) {
                    u64 av = a2[p];
#pragma unroll
                    for (int j = 0; j < 4; j++)
                        acc2[s][p][j] = fma2(av, bd[j], acc2[s][p][j]);
                }
            }
        }
        __syncthreads();
    }

#pragma unroll
    for (int s = 0; s < 2; s++) {
        const float* bias = s ? bv_ : bk_;
        float* Yb = (s ? Yv : Yk) + b * 262144;
#pragma unroll
        for (int p = 0; p < 4; p++) {
            float lo[4], hi[4];
#pragma unroll
            for (int j = 0; j < 4; j++) unpack2(acc2[s][p][j], lo[j], hi[j]);
            int r0 = m0 + ty * 8 + 2 * p;
            float b0 = bias[r0], b1 = bias[r0 + 1];
            float4 o0 = make_float4(lo[0] + b0, lo[1] + b0, lo[2] + b0, lo[3] + b0);
            float4 o1 = make_float4(hi[0] + b1, hi[1] + b1, hi[2] + b1, hi[3] + b1);
            *(float4*)&Yb[r0 * 1024 + n0 + tx * 4]       = o0;
            *(float4*)&Yb[(r0 + 1) * 1024 + n0 + tx * 4] = o1;
        }
    }
}

// ---------------- offset pipeline -------------------------------------------
__global__ __launch_bounds__(256)
void offset_kernel(const float* __restrict__ q, const float* __restrict__ w_dw,
                   const float* __restrict__ b_dw, const float* __restrict__ ln_g,
                   const float* __restrict__ ln_b, const float* __restrict__ wpj,
                   float* __restrict__ pos_buf, float* __restrict__ out_pos,
                   float* __restrict__ out_ref)
{
    __shared__ float sw[1600];
    __shared__ float sb[64], sg[64], sbt[64], spj0[64], spj1[64];
    const int tid = threadIdx.x;
    for (int t = tid; t < 1600; t += 256) sw[t] = w_dw[t];
    if (tid < 64) {
        sb[tid] = b_dw[tid]; sg[tid] = ln_g[tid]; sbt[tid] = ln_b[tid];
        spj0[tid] = wpj[tid]; spj1[tid] = wpj[64 + tid];
    }
    __syncthreads();

    const int pix = blockIdx.x * 256 + tid;
    const int bg  = pix >> 10;
    const int p   = pix & 1023;
    const int i   = p >> 5, j = p & 31;
    const float* qb = q + bg * 65536;

    float s1 = 0.f, s2 = 0.f;
    for (int c = 0; c < 64; c++) {
        const float* qc = qb + c * 1024;
        const float* wc = sw + c * 25;
        float a = sb[c];
#pragma unroll
        for (int dy = 0; dy < 5; dy++) {
            int yy = i + dy - 2;
            if ((unsigned)yy > 31u) continue;
            const float* qr = qc + yy * 32;
#pragma unroll
            for (int dx = 0; dx < 5; dx++) {
                int xx = j + dx - 2;
                if ((unsigned)xx > 31u) continue;
                a = fmaf(qr[xx], wc[dy * 5 + dx], a);
            }
        }
        s1 += a;
        s2 = fmaf(a, a, s2);
    }
    float mu   = s1 * 0.015625f;
    float var  = s2 * 0.015625f - mu * mu;
    float rstd = rsqrtf(var + 1e-5f);

    float o0 = 0.f, o1 = 0.f;
    for (int c = 0; c < 64; c++) {
        const float* qc = qb + c * 1024;
        const float* wc = sw + c * 25;
        float a = sb[c];
#pragma unroll
        for (int dy = 0; dy < 5; dy++) {
            int yy = i + dy - 2;
            if ((unsigned)yy > 31u) continue;
            const float* qr = qc + yy * 32;
#pragma unroll
            for (int dx = 0; dx < 5; dx++) {
                int xx = j + dx - 2;
                if ((unsigned)xx > 31u) continue;
                a = fmaf(qr[xx], wc[dy * 5 + dx], a);
            }
        }
        float t  = fmaf((a - mu) * rstd, sg[c], sbt[c]);
        float gl = 0.5f * t * (1.f + erff(t * 0.70710678118654752f));
        o0 = fmaf(gl, spj0[c], o0);
        o1 = fmaf(gl, spj1[c], o1);
    }
    float off0 = tanhf(o0) * 0.0625f;
    float off1 = tanhf(o1) * 0.0625f;
    float r0 = (j + 0.5f) * 0.0625f - 1.f;
    float r1 = (i + 0.5f) * 0.0625f - 1.f;
    float P0 = off0 + r0, P1 = off1 + r1;

    pos_buf[pix * 2]     = P0;
    pos_buf[pix * 2 + 1] = P1;
    out_pos[pix * 2]     = P0;
    out_pos[pix * 2 + 1] = P1;
    out_ref[pix * 2]     = r0;
    out_ref[pix * 2 + 1] = r1;
}

// ---------------- bilinear sample of x at pos -> xs --------------------------
__global__ __launch_bounds__(256)
void sample_kernel(const float* __restrict__ x, const float* __restrict__ pos_buf,
                   float* __restrict__ xs)
{
    const int idx = blockIdx.x * 256 + threadIdx.x;
    const float P0 = pos_buf[idx * 2];
    const float P1 = pos_buf[idx * 2 + 1];
    const float gxp = (P1 + 1.f) * 15.5f;
    const float gyp = (P0 + 1.f) * 15.5f;
    float x0f = floorf(gxp), y0f = floorf(gyp);
    float x1f = x0f + 1.f,  y1f = y0f + 1.f;
    float wx1 = gxp - x0f, wx0 = 1.f - wx1;
    float wy1 = gyp - y0f, wy0 = 1.f - wy1;
    bool vx0 = (x0f >= 0.f) && (x0f <= 31.f);
    bool vx1 = (x1f >= 0.f) && (x1f <= 31.f);
    bool vy0 = (y0f >= 0.f) && (y0f <= 31.f);
    bool vy1 = (y1f >= 0.f) && (y1f <= 31.f);
    int X0 = (int)fminf(fmaxf(x0f, 0.f), 31.f);
    int X1 = (int)fminf(fmaxf(x1f, 0.f), 31.f);
    int Y0 = (int)fminf(fmaxf(y0f, 0.f), 31.f);
    int Y1 = (int)fminf(fmaxf(y1f, 0.f), 31.f);
    float w00 = (vy0 && vx0) ? wy0 * wx0 : 0.f;
    float w01 = (vy0 && vx1) ? wy0 * wx1 : 0.f;
    float w10 = (vy1 && vx0) ? wy1 * wx0 : 0.f;
    float w11 = (vy1 && vx1) ? wy1 * wx1 : 0.f;
    int i00 = Y0 * 32 + X0, i01 = Y0 * 32 + X1;
    int i10 = Y1 * 32 + X0, i11 = Y1 * 32 + X1;

    const int bg = idx >> 10, n = idx & 1023;
    const float* xb = x + bg * 65536;
    float* xo = xs + bg * 65536 + n;
    for (int c = 0; c < 64; c++) {
        const float* xc = xb + c * 1024;
        float vout = w00 * xc[i00] + w01 * xc[i01] + w10 * xc[i10] + w11 * xc[i11];
        xo[c * 1024] = vout;
    }
}

// ---------------- RPE bilinear, TRANSPOSED padded table sRpeT[ix*64+iy] -----
__device__ __forceinline__ float bias_T(const float* __restrict__ sR,
                                        float gyp, float gxp)
{
    int yi = __float2int_rd(gyp);
    int xi = __float2int_rd(gxp);
    float wy1 = gyp - (float)yi, wy0 = 1.f - wy1;
    float wx1 = gxp - (float)xi, wx0 = 1.f - wx1;
    int iy0 = yi & 63, iy1 = (yi + 1) & 63;
    int ix0 = xi & 63, ix1 = (xi + 1) & 63;
    const float* c0 = sR + (ix0 << 6);
    const float* c1 = sR + (ix1 << 6);
    float v00 = c0[iy0], v10 = c0[iy1];
    float v01 = c1[iy0], v11 = c1[iy1];
    float r0v = v00 * wy0 + v10 * wy1;
    float r1v = v01 * wy0 + v11 * wy1;
    return r0v * wx0 + r1v * wx1;
}

// ---------------- fused attention --------------------------------------------
__global__ __launch_bounds__(256, 2)
void attn_kernel(const float* __restrict__ q, const float* __restrict__ k,
                 const float* __restrict__ v, const float* __restrict__ rpe,
                 const float* __restrict__ pos, float* __restrict__ out)
{
    extern __shared__ float sm[];
    float* sQ   = sm;            // 2048
    float* sK   = sQ + 2048;     // 2112 (stride 66)
    float* sV   = sK + 2112;     // 2112 (stride 66)
    float* sP   = sV + 2112;     // 4096
    float* sPos = sP + 4096;     // 128
    float* sRpe = sPos + 128;    // 4096 transposed padded

    const int bh = blockIdx.y;
    const int b  = bh >> 3, h = bh & 7;
    const int g  = h >> 1;
    const int bg = b * 4 + g;
    const int m0 = blockIdx.x * 64;
    const float* rpe_h = rpe + h * 3969;

    const int tid  = threadIdx.x;
    const int w    = tid >> 5;
    const int lane = tid & 31;

    for (int t = tid; t < 4096; t += 256) sRpe[t] = 0.f;
    __syncthreads();
    for (int t = tid; t < 3969; t += 256) {
        int r = t / 63, c2 = t - r * 63;
        sRpe[(c2 << 6) + r] = rpe_h[t];      // transposed: [ix][iy]
    }

    const float* qh = q + (b * 256 + h * 32) * 1024;
    const float* kh = k + (b * 256 + h * 32) * 1024;
    const float* vh = v + (b * 256 + h * 32) * 1024;

    for (int idx = tid; idx < 2048; idx += 256) {
        int c = idx >> 6, mm = idx & 63;
        sQ[c * 64 + mm] = qh[c * 1024 + m0 + mm];
    }

    float L[8], cg0[8], cg1[8];
    u64 acc2[8];
#pragma unroll
    for (int r = 0; r < 8; r++) {
        L[r] = 0.f; acc2[r] = 0ULL;
        int mg = m0 + w * 8 + r;
        float qg0 = ((mg & 31) + 0.5f) * 0.0625f - 1.f;
        float qg1 = ((mg >> 5) + 0.5f) * 0.0625f - 1.f;
        cg0[r] = fmaf(qg0, 15.5f, 31.f);
        cg1[r] = fmaf(qg1, 15.5f, 31.f);
    }

    const float scale = 0.17677669529663687f;

    for (int nt = 0; nt < 16; nt++) {
        const int n0 = nt * 64;
        __syncthreads();
        for (int idx = tid; idx < 2048; idx += 256) {
            int c = idx >> 6, nn = idx & 63;
            sK[c * 66 + nn] = kh[c * 1024 + n0 + nn];
            sV[c * 66 + nn] = vh[c * 1024 + n0 + nn];
        }
        if (tid < 128) sPos[tid] = pos[bg * 2048 + n0 * 2 + tid];
        __syncthreads();

        // ---- scores: FFMA2 over m-pairs; q via LDS.128 broadcast
        u64 s2[4][2];
#pragma unroll
        for (int p = 0; p < 4; p++) { s2[p][0] = 0ULL; s2[p][1] = 0ULL; }
#pragma unroll
        for (int c = 0; c < 32; c++) {
            float2 kv = *(const float2*)&sK[c * 66 + (lane << 1)];
            u64 k0 = dup2(kv.x), k1 = dup2(kv.y);
            float4 qa = *(const float4*)&sQ[c * 64 + (w << 3)];
            float4 qb = *(const float4*)&sQ[c * 64 + (w << 3) + 4];
            u64 qp0 = pack2(qa.x, qa.y), qp1 = pack2(qa.z, qa.w);
            u64 qp2 = pack2(qb.x, qb.y), qp3 = pack2(qb.z, qb.w);
            s2[0][0] = fma2(qp0, k0, s2[0][0]); s2[0][1] = fma2(qp0, k1, s2[0][1]);
            s2[1][0] = fma2(qp1, k0, s2[1][0]); s2[1][1] = fma2(qp1, k1, s2[1][1]);
            s2[2][0] = fma2(qp2, k0, s2[2][0]); s2[2][1] = fma2(qp2, k1, s2[2][1]);
            s2[3][0] = fma2(qp3, k0, s2[3][0]); s2[3][1] = fma2(qp3, k1, s2[3][1]);
        }

        // ---- bias + shift-free exp
        float4 pA = *(const float4*)&sPos[lane << 2];
        float pb0 = 15.5f * pA.x, pb1 = 15.5f * pA.y;
        float pb2 = 15.5f * pA.z, pb3 = 15.5f * pA.w;
#pragma unroll
        for (int p = 0; p < 4; p++) {
            float sa0, sb0, sa1, sb1;
            unpack2(s2[p][0], sa0, sb0);
            unpack2(s2[p][1], sa1, sb1);
#pragma unroll
            for (int hrow = 0; hrow < 2; hrow++) {
                int r = 2 * p + hrow;
                float s0v = hrow ? sb0 : sa0;
                float s1v = hrow ? sb1 : sa1;
                float gy0 = cg0[r] - pb0, gx0 = cg1[r] - pb1;
                float gy1 = cg0[r] - pb2, gx1 = cg1[r] - pb3;
                float sc0 = fmaf(s0v, scale, bias_T(sRpe, gy0, gx0));
                float sc1 = fmaf(s1v, scale, bias_T(sRpe, gy1, gx1));
                float p0v = __expf(sc0);
                float p1v = __expf(sc1);
                L[r] += p0v + p1v;
                *(float2*)&sP[((w << 3) + r) * 64 + (lane << 1)] = make_float2(p0v, p1v);
            }
        }
        __syncwarp();

        // ---- PV: pp via LDS.128 (2 fma2 per load), vv conflict-free stride 66
#pragma unroll
        for (int nb = 0; nb < 64; nb += 4) {
            const u64* vv2 = (const u64*)&sV[lane * 66 + nb];
            u64 v01 = vv2[0], v23 = vv2[1];
#pragma unroll
            for (int r = 0; r < 8; r++) {
                float4 pp4 = *(const float4*)&sP[((w << 3) + r) * 64 + nb];
                u64 p01 = pack2(pp4.x, pp4.y);
                u64 p23 = pack2(pp4.z, pp4.w);
                acc2[r] = fma2(p01, v01, acc2[r]);
                acc2[r] = fma2(p23, v23, acc2[r]);
            }
        }
    }

#pragma unroll
    for (int r = 0; r < 8; r++) {
        float Ls = L[r];
#pragma unroll
        for (int o = 16; o; o >>= 1) Ls += __shfl_xor_sync(0xffffffffu, Ls, o);
        float alo, ahi;
        unpack2(acc2[r], alo, ahi);
        out[(b * 256 + h * 32 + lane) * 1024 + m0 + (w << 3) + r] = (alo + ahi) / Ls;
    }
}

// ---------------- launch ----------------
extern "C" void kernel_launch(void* const* d_in, const int* in_sizes, int n_in,
                              void* d_out, int out_size)
{
    const float* x        = (const float*)d_in[0];
    const float* wq       = (const float*)d_in[1];
    const float* bq       = (const float*)d_in[2];
    const float* w_off_dw = (const float*)d_in[3];
    const float* b_off_dw = (const float*)d_in[4];
    const float* ln_g     = (const float*)d_in[5];
    const float* ln_b     = (const float*)d_in[6];
    const float* w_off_pj = (const float*)d_in[7];
    const float* wk       = (const float*)d_in[8];
    const float* bk       = (const float*)d_in[9];
    const float* wv       = (const float*)d_in[10];
    const float* bv       = (const float*)d_in[11];
    const float* wo       = (const float*)d_in[12];
    const float* bo       = (const float*)d_in[13];
    const float* rpe      = (const float*)d_in[14];
    float* out = (float*)d_out;

    float *qb, *xsb, *kb, *vb, *ob, *posb;
    cudaGetSymbolAddress((void**)&qb,   g_q);
    cudaGetSymbolAddress((void**)&xsb,  g_xs);
    cudaGetSymbolAddress((void**)&kb,   g_k);
    cudaGetSymbolAddress((void**)&vb,   g_v);
    cudaGetSymbolAddress((void**)&ob,   g_o);
    cudaGetSymbolAddress((void**)&posb, g_pos);

    const int attn_smem = 58368;
    cudaFuncSetAttribute(attn_kernel, cudaFuncAttributeMaxDynamicSharedMemorySize, attn_smem);

    const dim3 gg(16, 2, 4);

    gemm_conv<<<gg, 256>>>(wq, x, bq, qb);
    offset_kernel<<<64, 256>>>(qb, w_off_dw, b_off_dw, ln_g, ln_b, w_off_pj,
                               posb, out + 1048576, out + 1048576 + 32768);
    sample_kernel<<<64, 256>>>(x, posb, xsb);
    gemm_kv<<<gg, 256>>>(wk, bk, kb, wv, bv, vb, xsb);
    attn_kernel<<<dim3(16, 32), 256, attn_smem>>>(qb, kb, vb, rpe, posb, ob);
    gemm_conv<<<gg, 256>>>(wo, ob, bo, out);
}

// round 5
// speedup vs baseline: 1.1110x; 1.1110x over previous
#include <cuda_runtime.h>
#include <math.h>

// B=4, C=256, H=W=32, NH=8, HC=32, G=4, GC=64, ns=1024, KK=5, ORF=2
typedef unsigned long long u64;

__device__ __forceinline__ u64 fma2(u64 a, u64 b, u64 c) {
    u64 d;
    asm("fma.rn.f32x2 %0, %1, %2, %3;" : "=l"(d) : "l"(a), "l"(b), "l"(c));
    return d;
}
__device__ __forceinline__ u64 pack2(float lo, float hi) {
    u64 r;
    asm("mov.b64 %0, {%1, %2};" : "=l"(r) : "f"(lo), "f"(hi));
    return r;
}
__device__ __forceinline__ u64 dup2(float x) { return pack2(x, x); }
__device__ __forceinline__ void unpack2(u64 a, float& lo, float& hi) {
    asm("mov.b64 {%0, %1}, %2;" : "=f"(lo), "=f"(hi) : "l"(a));
}

// ---------------- scratch ----------------
__device__ float g_q [4 * 256 * 1024];
__device__ float g_xs[4 * 256 * 1024];
__device__ float g_k [4 * 256 * 1024];
__device__ float g_v [4 * 256 * 1024];
__device__ float g_o [4 * 256 * 1024];
__device__ float g_pos[16 * 1024 * 2];

// ---------------- SGEMM core (128x64 tile, FFMA2 over m-pairs) --------------
__device__ __forceinline__ void gemm_body(const float* __restrict__ Wm,
                                          const float* __restrict__ Xb,
                                          const float* __restrict__ bias,
                                          float* __restrict__ Yb,
                                          int m0, int n0)
{
    __shared__ float As[16][132];
    __shared__ float Bs[16][64];

    const int tid = threadIdx.x;
    const int tx = tid & 15;
    const int ty = tid >> 4;

    const int am = tid >> 1;
    const int ak = (tid & 1) * 8;
    const int bn = tid & 63;
    const int bk = (tid >> 6) * 4;

    u64 acc2[4][4];
#pragma unroll
    for (int p = 0; p < 4; p++)
#pragma unroll
        for (int j = 0; j < 4; j++) acc2[p][j] = 0ULL;

    float4 wa, wb;
    float  xr[4];
    {
        const float* wp = &Wm[(m0 + am) * 256 + ak];
        wa = *(const float4*)wp;
        wb = *(const float4*)(wp + 4);
#pragma unroll
        for (int u = 0; u < 4; u++) xr[u] = Xb[(bk + u) * 1024 + n0 + bn];
    }

    for (int k0 = 0; k0 < 256; k0 += 16) {
        As[ak + 0][am] = wa.x; As[ak + 1][am] = wa.y;
        As[ak + 2][am] = wa.z; As[ak + 3][am] = wa.w;
        As[ak + 4][am] = wb.x; As[ak + 5][am] = wb.y;
        As[ak + 6][am] = wb.z; As[ak + 7][am] = wb.w;
#pragma unroll
        for (int u = 0; u < 4; u++) Bs[bk + u][bn] = xr[u];
        __syncthreads();

        if (k0 + 16 < 256) {
            const float* wp = &Wm[(m0 + am) * 256 + k0 + 16 + ak];
            wa = *(const float4*)wp;
            wb = *(const float4*)(wp + 4);
#pragma unroll
            for (int u = 0; u < 4; u++)
                xr[u] = Xb[(k0 + 16 + bk + u) * 1024 + n0 + bn];
        }

#pragma unroll
        for (int kk = 0; kk < 16; kk++) {
            const u64* a2 = (const u64*)&As[kk][ty * 8];
            float4 b4 = *(const float4*)&Bs[kk][tx * 4];
            u64 bd[4] = {dup2(b4.x), dup2(b4.y), dup2(b4.z), dup2(b4.w)};
#pragma unroll
            for (int p = 0; p < 4; p++) {
                u64 av = a2[p];
#pragma unroll
                for (int j = 0; j < 4; j++)
                    acc2[p][j] = fma2(av, bd[j], acc2[p][j]);
            }
        }
        __syncthreads();
    }

#pragma unroll
    for (int p = 0; p < 4; p++) {
        float lo[4], hi[4];
#pragma unroll
        for (int j = 0; j < 4; j++) unpack2(acc2[p][j], lo[j], hi[j]);
        int r0 = m0 + ty * 8 + 2 * p;
        float b0 = bias[r0], b1 = bias[r0 + 1];
        float4 o0 = make_float4(lo[0] + b0, lo[1] + b0, lo[2] + b0, lo[3] + b0);
        float4 o1 = make_float4(hi[0] + b1, hi[1] + b1, hi[2] + b1, hi[3] + b1);
        *(float4*)&Yb[r0 * 1024 + n0 + tx * 4]       = o0;
        *(float4*)&Yb[(r0 + 1) * 1024 + n0 + tx * 4] = o1;
    }
}

__global__ __launch_bounds__(256)
void gemm_conv(const float* __restrict__ Wm, const float* __restrict__ X,
               const float* __restrict__ bias, float* __restrict__ Y)
{
    gemm_body(Wm, X + blockIdx.z * 262144, bias, Y + blockIdx.z * 262144,
              blockIdx.y * 128, blockIdx.x * 64);
}

// grid (16, 4, 4): y<2 -> K projection, y>=2 -> V projection
__global__ __launch_bounds__(256)
void gemm_kv(const float* __restrict__ Wk, const float* __restrict__ bk,
             float* __restrict__ Yk,
             const float* __restrict__ Wv, const float* __restrict__ bv,
             float* __restrict__ Yv, const float* __restrict__ X)
{
    const int my = blockIdx.y;
    const float* Xb = X + blockIdx.z * 262144;
    if (my < 2)
        gemm_body(Wk, Xb, bk, Yk + blockIdx.z * 262144, my * 128, blockIdx.x * 64);
    else
        gemm_body(Wv, Xb, bv, Yv + blockIdx.z * 262144, (my - 2) * 128, blockIdx.x * 64);
}

// ---------------- offset pipeline: smem-staged conv, activations cached -----
// 64 blocks x 256 threads; block bi covers bg = bi>>2, rows i0 = (bi&3)*8 .. +7
// dynamic smem: simg [64][384] (12 halo rows x 32 cols) + sa [64][256] = 163840 B
__global__ __launch_bounds__(256)
void offset_kernel(const float* __restrict__ q, const float* __restrict__ w_dw,
                   const float* __restrict__ b_dw, const float* __restrict__ ln_g,
                   const float* __restrict__ ln_b, const float* __restrict__ wpj,
                   float* __restrict__ pos_buf, float* __restrict__ out_pos,
                   float* __restrict__ out_ref)
{
    extern __shared__ float dsm[];
    float* simg = dsm;               // [c][384]
    float* sa   = dsm + 64 * 384;    // [c][256]

    __shared__ float sw[1600];
    __shared__ float sb[64], sg[64], sbt[64], spj0[64], spj1[64];

    const int tid = threadIdx.x;
    for (int t = tid; t < 1600; t += 256) sw[t] = w_dw[t];
    if (tid < 64) {
        sb[tid] = b_dw[tid]; sg[tid] = ln_g[tid]; sbt[tid] = ln_b[tid];
        spj0[tid] = wpj[tid]; spj1[tid] = wpj[64 + tid];
    }

    const int bi = blockIdx.x;
    const int bg = bi >> 2;
    const int i0 = (bi & 3) * 8;
    const float* qb = q + bg * 65536;

    // stage 12 halo rows of all 64 channels, zero-padded vertically
    for (int t = tid; t < 24576; t += 256) {
        int c  = t / 384;
        int r2 = t - c * 384;
        int yy = i0 - 2 + (r2 >> 5);
        int col = r2 & 31;
        float vv = 0.f;
        if ((unsigned)yy < 32u) vv = qb[c * 1024 + yy * 32 + col];
        simg[c * 384 + r2] = vv;
    }
    __syncthreads();

    const int li = tid >> 5;   // local row 0..7
    const int j  = tid & 31;
    const int i  = i0 + li;

    // pass A: conv per channel, stash activation, accumulate LN stats
    float s1 = 0.f, s2 = 0.f;
    for (int c = 0; c < 64; c++) {
        const float* ic = simg + c * 384 + li * 32;
        const float* wc = sw + c * 25;
        float a = sb[c];
#pragma unroll
        for (int dy = 0; dy < 5; dy++) {
            const float* irow = ic + dy * 32;
#pragma unroll
            for (int dx = 0; dx < 5; dx++) {
                int xx = j + dx - 2;
                float vv = ((unsigned)xx < 32u) ? irow[xx] : 0.f;
                a = fmaf(vv, wc[dy * 5 + dx], a);
            }
        }
        s1 += a;
        s2 = fmaf(a, a, s2);
        sa[c * 256 + tid] = a;
    }
    float mu   = s1 * 0.015625f;
    float var  = s2 * 0.015625f - mu * mu;
    float rstd = rsqrtf(var + 1e-5f);

    // pass B: LN + GELU + project (reads cached activations)
    float o0 = 0.f, o1 = 0.f;
    for (int c = 0; c < 64; c++) {
        float a  = sa[c * 256 + tid];
        float t2 = fmaf((a - mu) * rstd, sg[c], sbt[c]);
        float gl = 0.5f * t2 * (1.f + erff(t2 * 0.70710678118654752f));
        o0 = fmaf(gl, spj0[c], o0);
        o1 = fmaf(gl, spj1[c], o1);
    }
    float off0 = tanhf(o0) * 0.0625f;
    float off1 = tanhf(o1) * 0.0625f;
    float r0 = (j + 0.5f) * 0.0625f - 1.f;
    float r1 = (i + 0.5f) * 0.0625f - 1.f;
    float P0 = off0 + r0, P1 = off1 + r1;

    const int pix = bi * 256 + tid;    // == bg*1024 + i*32 + j
    pos_buf[pix * 2]     = P0;
    pos_buf[pix * 2 + 1] = P1;
    out_pos[pix * 2]     = P0;
    out_pos[pix * 2 + 1] = P1;
    out_ref[pix * 2]     = r0;
    out_ref[pix * 2 + 1] = r1;
}

// ---------------- bilinear sample of x at pos -> xs --------------------------
__global__ __launch_bounds__(256)
void sample_kernel(const float* __restrict__ x, const float* __restrict__ pos_buf,
                   float* __restrict__ xs)
{
    const int idx = blockIdx.x * 256 + threadIdx.x;
    const float P0 = pos_buf[idx * 2];
    const float P1 = pos_buf[idx * 2 + 1];
    const float gxp = (P1 + 1.f) * 15.5f;
    const float gyp = (P0 + 1.f) * 15.5f;
    float x0f = floorf(gxp), y0f = floorf(gyp);
    float x1f = x0f + 1.f,  y1f = y0f + 1.f;
    float wx1 = gxp - x0f, wx0 = 1.f - wx1;
    float wy1 = gyp - y0f, wy0 = 1.f - wy1;
    bool vx0 = (x0f >= 0.f) && (x0f <= 31.f);
    bool vx1 = (x1f >= 0.f) && (x1f <= 31.f);
    bool vy0 = (y0f >= 0.f) && (y0f <= 31.f);
    bool vy1 = (y1f >= 0.f) && (y1f <= 31.f);
    int X0 = (int)fminf(fmaxf(x0f, 0.f), 31.f);
    int X1 = (int)fminf(fmaxf(x1f, 0.f), 31.f);
    int Y0 = (int)fminf(fmaxf(y0f, 0.f), 31.f);
    int Y1 = (int)fminf(fmaxf(y1f, 0.f), 31.f);
    float w00 = (vy0 && vx0) ? wy0 * wx0 : 0.f;
    float w01 = (vy0 && vx1) ? wy0 * wx1 : 0.f;
    float w10 = (vy1 && vx0) ? wy1 * wx0 : 0.f;
    float w11 = (vy1 && vx1) ? wy1 * wx1 : 0.f;
    int i00 = Y0 * 32 + X0, i01 = Y0 * 32 + X1;
    int i10 = Y1 * 32 + X0, i11 = Y1 * 32 + X1;

    const int bg = idx >> 10, n = idx & 1023;
    const float* xb = x + bg * 65536;
    float* xo = xs + bg * 65536 + n;
    for (int c = 0; c < 64; c++) {
        const float* xc = xb + c * 1024;
        float vout = w00 * xc[i00] + w01 * xc[i01] + w10 * xc[i10] + w11 * xc[i11];
        xo[c * 1024] = vout;
    }
}

// ---------------- RPE bilinear, TRANSPOSED padded table sRpeT[ix*64+iy] -----
__device__ __forceinline__ float bias_T(const float* __restrict__ sR,
                                        float gyp, float gxp)
{
    int yi = __float2int_rd(gyp);
    int xi = __float2int_rd(gxp);
    float wy1 = gyp - (float)yi, wy0 = 1.f - wy1;
    float wx1 = gxp - (float)xi, wx0 = 1.f - wx1;
    int iy0 = yi & 63, iy1 = (yi + 1) & 63;
    int ix0 = xi & 63, ix1 = (xi + 1) & 63;
    const float* c0 = sR + (ix0 << 6);
    const float* c1 = sR + (ix1 << 6);
    float v00 = c0[iy0], v10 = c0[iy1];
    float v01 = c1[iy0], v11 = c1[iy1];
    float r0v = v00 * wy0 + v10 * wy1;
    float r1v = v01 * wy0 + v11 * wy1;
    return r0v * wx0 + r1v * wx1;
}

// ---------------- fused attention (occ target 3) ------------------------------
__global__ __launch_bounds__(256, 3)
void attn_kernel(const float* __restrict__ q, const float* __restrict__ k,
                 const float* __restrict__ v, const float* __restrict__ rpe,
                 const float* __restrict__ pos, float* __restrict__ out)
{
    extern __shared__ float sm[];
    float* sQ   = sm;            // 2048
    float* sK   = sQ + 2048;     // 2112 (stride 66)
    float* sV   = sK + 2112;     // 2112 (stride 66)
    float* sP   = sV + 2112;     // 4096
    float* sPos = sP + 4096;     // 128
    float* sRpe = sPos + 128;    // 4096 transposed padded

    const int bh = blockIdx.y;
    const int b  = bh >> 3, h = bh & 7;
    const int g  = h >> 1;
    const int bg = b * 4 + g;
    const int m0 = blockIdx.x * 64;
    const float* rpe_h = rpe + h * 3969;

    const int tid  = threadIdx.x;
    const int w    = tid >> 5;
    const int lane = tid & 31;

    for (int t = tid; t < 4096; t += 256) sRpe[t] = 0.f;
    __syncthreads();
    for (int t = tid; t < 3969; t += 256) {
        int r = t / 63, c2 = t - r * 63;
        sRpe[(c2 << 6) + r] = rpe_h[t];      // transposed: [ix][iy]
    }

    const float* qh = q + (b * 256 + h * 32) * 1024;
    const float* kh = k + (b * 256 + h * 32) * 1024;
    const float* vh = v + (b * 256 + h * 32) * 1024;

    for (int idx = tid; idx < 2048; idx += 256) {
        int c = idx >> 6, mm = idx & 63;
        sQ[c * 64 + mm] = qh[c * 1024 + m0 + mm];
    }

    float L[8], cg0[8], cg1[8];
    u64 acc2[8];
#pragma unroll
    for (int r = 0; r < 8; r++) {
        L[r] = 0.f; acc2[r] = 0ULL;
        int mg = m0 + w * 8 + r;
        float qg0 = ((mg & 31) + 0.5f) * 0.0625f - 1.f;
        float qg1 = ((mg >> 5) + 0.5f) * 0.0625f - 1.f;
        cg0[r] = fmaf(qg0, 15.5f, 31.f);
        cg1[r] = fmaf(qg1, 15.5f, 31.f);
    }

    const float scale = 0.17677669529663687f;

    for (int nt = 0; nt < 16; nt++) {
        const int n0 = nt * 64;
        __syncthreads();
        for (int idx = tid; idx < 2048; idx += 256) {
            int c = idx >> 6, nn = idx & 63;
            sK[c * 66 + nn] = kh[c * 1024 + n0 + nn];
            sV[c * 66 + nn] = vh[c * 1024 + n0 + nn];
        }
        if (tid < 128) sPos[tid] = pos[bg * 2048 + n0 * 2 + tid];
        __syncthreads();

        // ---- scores: FFMA2 over m-pairs; q via LDS.128 broadcast
        u64 s2[4][2];
#pragma unroll
        for (int p = 0; p < 4; p++) { s2[p][0] = 0ULL; s2[p][1] = 0ULL; }
#pragma unroll
        for (int c = 0; c < 32; c++) {
            float2 kv = *(const float2*)&sK[c * 66 + (lane << 1)];
            u64 k0 = dup2(kv.x), k1 = dup2(kv.y);
            float4 qa = *(const float4*)&sQ[c * 64 + (w << 3)];
            float4 qb = *(const float4*)&sQ[c * 64 + (w << 3) + 4];
            u64 qp0 = pack2(qa.x, qa.y), qp1 = pack2(qa.z, qa.w);
            u64 qp2 = pack2(qb.x, qb.y), qp3 = pack2(qb.z, qb.w);
            s2[0][0] = fma2(qp0, k0, s2[0][0]); s2[0][1] = fma2(qp0, k1, s2[0][1]);
            s2[1][0] = fma2(qp1, k0, s2[1][0]); s2[1][1] = fma2(qp1, k1, s2[1][1]);
            s2[2][0] = fma2(qp2, k0, s2[2][0]); s2[2][1] = fma2(qp2, k1, s2[2][1]);
            s2[3][0] = fma2(qp3, k0, s2[3][0]); s2[3][1] = fma2(qp3, k1, s2[3][1]);
        }

        // ---- bias + shift-free exp
        float4 pA = *(const float4*)&sPos[lane << 2];
        float pb0 = 15.5f * pA.x, pb1 = 15.5f * pA.y;
        float pb2 = 15.5f * pA.z, pb3 = 15.5f * pA.w;
#pragma unroll
        for (int p = 0; p < 4; p++) {
            float sa0, sb0, sa1, sb1;
            unpack2(s2[p][0], sa0, sb0);
            unpack2(s2[p][1], sa1, sb1);
#pragma unroll
            for (int hrow = 0; hrow < 2; hrow++) {
                int r = 2 * p + hrow;
                float s0v = hrow ? sb0 : sa0;
                float s1v = hrow ? sb1 : sa1;
                float gy0 = cg0[r] - pb0, gx0 = cg1[r] - pb1;
                float gy1 = cg0[r] - pb2, gx1 = cg1[r] - pb3;
                float sc0 = fmaf(s0v, scale, bias_T(sRpe, gy0, gx0));
                float sc1 = fmaf(s1v, scale, bias_T(sRpe, gy1, gx1));
                float p0v = __expf(sc0);
                float p1v = __expf(sc1);
                L[r] += p0v + p1v;
                *(float2*)&sP[((w << 3) + r) * 64 + (lane << 1)] = make_float2(p0v, p1v);
            }
        }
        __syncwarp();

        // ---- PV
#pragma unroll
        for (int nb = 0; nb < 64; nb += 4) {
            const u64* vv2 = (const u64*)&sV[lane * 66 + nb];
            u64 v01 = vv2[0], v23 = vv2[1];
#pragma unroll
            for (int r = 0; r < 8; r++) {
                float4 pp4 = *(const float4*)&sP[((w << 3) + r) * 64 + nb];
                u64 p01 = pack2(pp4.x, pp4.y);
                u64 p23 = pack2(pp4.z, pp4.w);
                acc2[r] = fma2(p01, v01, acc2[r]);
                acc2[r] = fma2(p23, v23, acc2[r]);
            }
        }
    }

#pragma unroll
    for (int r = 0; r < 8; r++) {
        float Ls = L[r];
#pragma unroll
        for (int o = 16; o; o >>= 1) Ls += __shfl_xor_sync(0xffffffffu, Ls, o);
        float alo, ahi;
        unpack2(acc2[r], alo, ahi);
        out[(b * 256 + h * 32 + lane) * 1024 + m0 + (w << 3) + r] = (alo + ahi) / Ls;
    }
}

// ---------------- launch ----------------
extern "C" void kernel_launch(void* const* d_in, const int* in_sizes, int n_in,
                              void* d_out, int out_size)
{
    const float* x        = (const float*)d_in[0];
    const float* wq       = (const float*)d_in[1];
    const float* bq       = (const float*)d_in[2];
    const float* w_off_dw = (const float*)d_in[3];
    const float* b_off_dw = (const float*)d_in[4];
    const float* ln_g     = (const float*)d_in[5];
    const float* ln_b     = (const float*)d_in[6];
    const float* w_off_pj = (const float*)d_in[7];
    const float* wk       = (const float*)d_in[8];
    const float* bk       = (const float*)d_in[9];
    const float* wv       = (const float*)d_in[10];
    const float* bv       = (const float*)d_in[11];
    const float* wo       = (const float*)d_in[12];
    const float* bo       = (const float*)d_in[13];
    const float* rpe      = (const float*)d_in[14];
    float* out = (float*)d_out;

    float *qb, *xsb, *kb, *vb, *ob, *posb;
    cudaGetSymbolAddress((void**)&qb,   g_q);
    cudaGetSymbolAddress((void**)&xsb,  g_xs);
    cudaGetSymbolAddress((void**)&kb,   g_k);
    cudaGetSymbolAddress((void**)&vb,   g_v);
    cudaGetSymbolAddress((void**)&ob,   g_o);
    cudaGetSymbolAddress((void**)&posb, g_pos);

    const int attn_smem = 58368;
    cudaFuncSetAttribute(attn_kernel, cudaFuncAttributeMaxDynamicSharedMemorySize, attn_smem);
    const int off_smem = 163840;   // simg 64*384 + sa 64*256 floats
    cudaFuncSetAttribute(offset_kernel, cudaFuncAttributeMaxDynamicSharedMemorySize, off_smem);

    const dim3 gg(16, 2, 4);

    gemm_conv<<<gg, 256>>>(wq, x, bq, qb);
    offset_kernel<<<64, 256, off_smem>>>(qb, w_off_dw, b_off_dw, ln_g, ln_b, w_off_pj,
                                         posb, out + 1048576, out + 1048576 + 32768);
    sample_kernel<<<64, 256>>>(x, posb, xsb);
    gemm_kv<<<dim3(16, 4, 4), 256>>>(wk, bk, kb, wv, bv, vb, xsb);
    attn_kernel<<<dim3(16, 32), 256, attn_smem>>>(qb, kb, vb, rpe, posb, ob);
    gemm_conv<<<gg, 256>>>(wo, ob, bo, out);
}

// round 6
// speedup vs baseline: 1.5665x; 1.4100x over previous
#include <cuda_runtime.h>
#include <math.h>
#include <stdint.h>

// B=4, C=256, H=W=32, NH=8, HC=32, G=4, GC=64, ns=1024, KK=5, ORF=2
typedef unsigned long long u64;

__device__ __forceinline__ u64 fma2(u64 a, u64 b, u64 c) {
    u64 d;
    asm("fma.rn.f32x2 %0, %1, %2, %3;" : "=l"(d) : "l"(a), "l"(b), "l"(c));
    return d;
}
__device__ __forceinline__ u64 pack2(float lo, float hi) {
    u64 r;
    asm("mov.b64 %0, {%1, %2};" : "=l"(r) : "f"(lo), "f"(hi));
    return r;
}
__device__ __forceinline__ u64 dup2(float x) { return pack2(x, x); }
__device__ __forceinline__ void unpack2(u64 a, float& lo, float& hi) {
    asm("mov.b64 {%0, %1}, %2;" : "=f"(lo), "=f"(hi) : "l"(a));
}
__device__ __forceinline__ uint32_t cvt_tf32(float x) {
    uint32_t r;
    asm("cvt.rna.tf32.f32 %0, %1;" : "=r"(r) : "f"(x));
    return r;
}
__device__ __forceinline__ void mma_tf32(float c[4],
                                         uint32_t a0, uint32_t a1, uint32_t a2, uint32_t a3,
                                         uint32_t b0, uint32_t b1) {
    asm("mma.sync.aligned.m16n8k8.row.col.f32.tf32.tf32.f32 "
        "{%0,%1,%2,%3}, {%4,%5,%6,%7}, {%8,%9}, {%0,%1,%2,%3};"
        : "+f"(c[0]), "+f"(c[1]), "+f"(c[2]), "+f"(c[3])
        : "r"(a0), "r"(a1), "r"(a2), "r"(a3), "r"(b0), "r"(b1));
}

// ---------------- scratch ----------------
__device__ float g_q [4 * 256 * 1024];
__device__ float g_xs[4 * 256 * 1024];
__device__ float g_k [4 * 256 * 1024];
__device__ float g_v [4 * 256 * 1024];
__device__ float g_o [4 * 256 * 1024];
__device__ float g_pos[16 * 1024 * 2];

// ---------------- SGEMM core (128x64 tile, FFMA2 over m-pairs) --------------
__device__ __forceinline__ void gemm_body(const float* __restrict__ Wm,
                                          const float* __restrict__ Xb,
                                          const float* __restrict__ bias,
                                          float* __restrict__ Yb,
                                          int m0, int n0)
{
    __shared__ float As[16][132];
    __shared__ float Bs[16][64];

    const int tid = threadIdx.x;
    const int tx = tid & 15;
    const int ty = tid >> 4;

    const int am = tid >> 1;
    const int ak = (tid & 1) * 8;
    const int bn = tid & 63;
    const int bk = (tid >> 6) * 4;

    u64 acc2[4][4];
#pragma unroll
    for (int p = 0; p < 4; p++)
#pragma unroll
        for (int j = 0; j < 4; j++) acc2[p][j] = 0ULL;

    float4 wa, wb;
    float  xr[4];
    {
        const float* wp = &Wm[(m0 + am) * 256 + ak];
        wa = *(const float4*)wp;
        wb = *(const float4*)(wp + 4);
#pragma unroll
        for (int u = 0; u < 4; u++) xr[u] = Xb[(bk + u) * 1024 + n0 + bn];
    }

    for (int k0 = 0; k0 < 256; k0 += 16) {
        As[ak + 0][am] = wa.x; As[ak + 1][am] = wa.y;
        As[ak + 2][am] = wa.z; As[ak + 3][am] = wa.w;
        As[ak + 4][am] = wb.x; As[ak + 5][am] = wb.y;
        As[ak + 6][am] = wb.z; As[ak + 7][am] = wb.w;
#pragma unroll
        for (int u = 0; u < 4; u++) Bs[bk + u][bn] = xr[u];
        __syncthreads();

        if (k0 + 16 < 256) {
            const float* wp = &Wm[(m0 + am) * 256 + k0 + 16 + ak];
            wa = *(const float4*)wp;
            wb = *(const float4*)(wp + 4);
#pragma unroll
            for (int u = 0; u < 4; u++)
                xr[u] = Xb[(k0 + 16 + bk + u) * 1024 + n0 + bn];
        }

#pragma unroll
        for (int kk = 0; kk < 16; kk++) {
            const u64* a2 = (const u64*)&As[kk][ty * 8];
            float4 b4 = *(const float4*)&Bs[kk][tx * 4];
            u64 bd[4] = {dup2(b4.x), dup2(b4.y), dup2(b4.z), dup2(b4.w)};
#pragma unroll
            for (int p = 0; p < 4; p++) {
                u64 av = a2[p];
#pragma unroll
                for (int j = 0; j < 4; j++)
                    acc2[p][j] = fma2(av, bd[j], acc2[p][j]);
            }
        }
        __syncthreads();
    }

#pragma unroll
    for (int p = 0; p < 4; p++) {
        float lo[4], hi[4];
#pragma unroll
        for (int j = 0; j < 4; j++) unpack2(acc2[p][j], lo[j], hi[j]);
        int r0 = m0 + ty * 8 + 2 * p;
        float b0 = bias[r0], b1 = bias[r0 + 1];
        float4 o0 = make_float4(lo[0] + b0, lo[1] + b0, lo[2] + b0, lo[3] + b0);
        float4 o1 = make_float4(hi[0] + b1, hi[1] + b1, hi[2] + b1, hi[3] + b1);
        *(float4*)&Yb[r0 * 1024 + n0 + tx * 4]       = o0;
        *(float4*)&Yb[(r0 + 1) * 1024 + n0 + tx * 4] = o1;
    }
}

__global__ __launch_bounds__(256)
void gemm_conv(const float* __restrict__ Wm, const float* __restrict__ X,
               const float* __restrict__ bias, float* __restrict__ Y)
{
    gemm_body(Wm, X + blockIdx.z * 262144, bias, Y + blockIdx.z * 262144,
              blockIdx.y * 128, blockIdx.x * 64);
}

// grid (16, 4, 4): y<2 -> K projection, y>=2 -> V projection
__global__ __launch_bounds__(256)
void gemm_kv(const float* __restrict__ Wk, const float* __restrict__ bk,
             float* __restrict__ Yk,
             const float* __restrict__ Wv, const float* __restrict__ bv,
             float* __restrict__ Yv, const float* __restrict__ X)
{
    const int my = blockIdx.y;
    const float* Xb = X + blockIdx.z * 262144;
    if (my < 2)
        gemm_body(Wk, Xb, bk, Yk + blockIdx.z * 262144, my * 128, blockIdx.x * 64);
    else
        gemm_body(Wv, Xb, bv, Yv + blockIdx.z * 262144, (my - 2) * 128, blockIdx.x * 64);
}

// ---------------- offset pipeline: smem-staged conv, activations cached -----
__global__ __launch_bounds__(256)
void offset_kernel(const float* __restrict__ q, const float* __restrict__ w_dw,
                   const float* __restrict__ b_dw, const float* __restrict__ ln_g,
                   const float* __restrict__ ln_b, const float* __restrict__ wpj,
                   float* __restrict__ pos_buf, float* __restrict__ out_pos,
                   float* __restrict__ out_ref)
{
    extern __shared__ float dsm[];
    float* simg = dsm;               // [c][384]
    float* sa   = dsm + 64 * 384;    // [c][256]

    __shared__ float sw[1600];
    __shared__ float sb[64], sg[64], sbt[64], spj0[64], spj1[64];

    const int tid = threadIdx.x;
    for (int t = tid; t < 1600; t += 256) sw[t] = w_dw[t];
    if (tid < 64) {
        sb[tid] = b_dw[tid]; sg[tid] = ln_g[tid]; sbt[tid] = ln_b[tid];
        spj0[tid] = wpj[tid]; spj1[tid] = wpj[64 + tid];
    }

    const int bi = blockIdx.x;
    const int bg = bi >> 2;
    const int i0 = (bi & 3) * 8;
    const float* qb = q + bg * 65536;

    for (int t = tid; t < 24576; t += 256) {
        int c  = t / 384;
        int r2 = t - c * 384;
        int yy = i0 - 2 + (r2 >> 5);
        int col = r2 & 31;
        float vv = 0.f;
        if ((unsigned)yy < 32u) vv = qb[c * 1024 + yy * 32 + col];
        simg[c * 384 + r2] = vv;
    }
    __syncthreads();

    const int li = tid >> 5;
    const int j  = tid & 31;
    const int i  = i0 + li;

    float s1 = 0.f, s2 = 0.f;
    for (int c = 0; c < 64; c++) {
        const float* ic = simg + c * 384 + li * 32;
        const float* wc = sw + c * 25;
        float a = sb[c];
#pragma unroll
        for (int dy = 0; dy < 5; dy++) {
            const float* irow = ic + dy * 32;
#pragma unroll
            for (int dx = 0; dx < 5; dx++) {
                int xx = j + dx - 2;
                float vv = ((unsigned)xx < 32u) ? irow[xx] : 0.f;
                a = fmaf(vv, wc[dy * 5 + dx], a);
            }
        }
        s1 += a;
        s2 = fmaf(a, a, s2);
        sa[c * 256 + tid] = a;
    }
    float mu   = s1 * 0.015625f;
    float var  = s2 * 0.015625f - mu * mu;
    float rstd = rsqrtf(var + 1e-5f);

    float o0 = 0.f, o1 = 0.f;
    for (int c = 0; c < 64; c++) {
        float a  = sa[c * 256 + tid];
        float t2 = fmaf((a - mu) * rstd, sg[c], sbt[c]);
        float gl = 0.5f * t2 * (1.f + erff(t2 * 0.70710678118654752f));
        o0 = fmaf(gl, spj0[c], o0);
        o1 = fmaf(gl, spj1[c], o1);
    }
    float off0 = tanhf(o0) * 0.0625f;
    float off1 = tanhf(o1) * 0.0625f;
    float r0 = (j + 0.5f) * 0.0625f - 1.f;
    float r1 = (i + 0.5f) * 0.0625f - 1.f;
    float P0 = off0 + r0, P1 = off1 + r1;

    const int pix = bi * 256 + tid;
    pos_buf[pix * 2]     = P0;
    pos_buf[pix * 2 + 1] = P1;
    out_pos[pix * 2]     = P0;
    out_pos[pix * 2 + 1] = P1;
    out_ref[pix * 2]     = r0;
    out_ref[pix * 2 + 1] = r1;
}

// ---------------- bilinear sample of x at pos -> xs --------------------------
__global__ __launch_bounds__(256)
void sample_kernel(const float* __restrict__ x, const float* __restrict__ pos_buf,
                   float* __restrict__ xs)
{
    const int idx = blockIdx.x * 256 + threadIdx.x;
    const float P0 = pos_buf[idx * 2];
    const float P1 = pos_buf[idx * 2 + 1];
    const float gxp = (P1 + 1.f) * 15.5f;
    const float gyp = (P0 + 1.f) * 15.5f;
    float x0f = floorf(gxp), y0f = floorf(gyp);
    float x1f = x0f + 1.f,  y1f = y0f + 1.f;
    float wx1 = gxp - x0f, wx0 = 1.f - wx1;
    float wy1 = gyp - y0f, wy0 = 1.f - wy1;
    bool vx0 = (x0f >= 0.f) && (x0f <= 31.f);
    bool vx1 = (x1f >= 0.f) && (x1f <= 31.f);
    bool vy0 = (y0f >= 0.f) && (y0f <= 31.f);
    bool vy1 = (y1f >= 0.f) && (y1f <= 31.f);
    int X0 = (int)fminf(fmaxf(x0f, 0.f), 31.f);
    int X1 = (int)fminf(fmaxf(x1f, 0.f), 31.f);
    int Y0 = (int)fminf(fmaxf(y0f, 0.f), 31.f);
    int Y1 = (int)fminf(fmaxf(y1f, 0.f), 31.f);
    float w00 = (vy0 && vx0) ? wy0 * wx0 : 0.f;
    float w01 = (vy0 && vx1) ? wy0 * wx1 : 0.f;
    float w10 = (vy1 && vx0) ? wy1 * wx0 : 0.f;
    float w11 = (vy1 && vx1) ? wy1 * wx1 : 0.f;
    int i00 = Y0 * 32 + X0, i01 = Y0 * 32 + X1;
    int i10 = Y1 * 32 + X0, i11 = Y1 * 32 + X1;

    const int bg = idx >> 10, n = idx & 1023;
    const float* xb = x + bg * 65536;
    float* xo = xs + bg * 65536 + n;
    for (int c = 0; c < 64; c++) {
        const float* xc = xb + c * 1024;
        float vout = w00 * xc[i00] + w01 * xc[i01] + w10 * xc[i10] + w11 * xc[i11];
        xo[c * 1024] = vout;
    }
}

// ---------------- RPE bilinear, TRANSPOSED padded table sRpeT[ix*64+iy] -----
__device__ __forceinline__ float bias_T(const float* __restrict__ sR,
                                        float gyp, float gxp)
{
    int yi = __float2int_rd(gyp);
    int xi = __float2int_rd(gxp);
    float wy1 = gyp - (float)yi, wy0 = 1.f - wy1;
    float wx1 = gxp - (float)xi, wx0 = 1.f - wx1;
    int iy0 = yi & 63, iy1 = (yi + 1) & 63;
    int ix0 = xi & 63, ix1 = (xi + 1) & 63;
    const float* c0 = sR + (ix0 << 6);
    const float* c1 = sR + (ix1 << 6);
    float v00 = c0[iy0], v10 = c0[iy1];
    float v01 = c1[iy0], v11 = c1[iy1];
    float r0v = v00 * wy0 + v10 * wy1;
    float r1v = v01 * wy0 + v11 * wy1;
    return r0v * wx0 + r1v * wx1;
}

// ---------------- fused attention on tensor cores (mma.sync tf32) ------------
// grid (8, 32): m-tile 128, 8 warps, warp w owns rows [w*16, w*16+16).
// smem words: sQ 128*36 | sK 64*36 | sV 64*36 (as [sample][chan]) | sP 128*68
//             | sPos 128 | sRpe 4096   => 22144 words = 88576 B, occ 2.
__global__ __launch_bounds__(256, 2)
void attn_mma(const float* __restrict__ q, const float* __restrict__ k,
              const float* __restrict__ v, const float* __restrict__ rpe,
              const float* __restrict__ pos, float* __restrict__ out)
{
    extern __shared__ float smf[];
    uint32_t* sQ  = (uint32_t*)smf;          // [m=128][c=32] stride 36
    uint32_t* sK  = sQ + 4608;               // [n=64][c=32]  stride 36
    uint32_t* sV  = sK + 2304;               // [s=64][ch=32] stride 36
    uint32_t* sP  = sV + 2304;               // [m=128][s=64] stride 68
    float* sPos = (float*)(sP + 8704);       // 128
    float* sRpe = sPos + 128;                // 4096

    const int bh = blockIdx.y;
    const int b  = bh >> 3, h = bh & 7;
    const int gq = h >> 1;
    const int bg = b * 4 + gq;
    const int m0 = blockIdx.x * 128;
    const float* rpe_h = rpe + h * 3969;

    const int tid  = threadIdx.x;
    const int w    = tid >> 5;
    const int lane = tid & 31;
    const int grp  = lane >> 2;     // fragment groupID (row within strip)
    const int tig  = lane & 3;      // thread in group

    // RPE table, transposed + padded
    for (int t = tid; t < 4096; t += 256) sRpe[t] = 0.f;
    __syncthreads();
    for (int t = tid; t < 3969; t += 256) {
        int r = t / 63, c2 = t - r * 63;
        sRpe[(c2 << 6) + r] = rpe_h[t];
    }

    const float* qh = q + (b * 256 + h * 32) * 1024;
    const float* kh = k + (b * 256 + h * 32) * 1024;
    const float* vh = v + (b * 256 + h * 32) * 1024;

    // stage Q transposed -> [m][c], tf32
    for (int idx = tid; idx < 4096; idx += 256) {
        int c = idx >> 7, mm = idx & 127;
        sQ[mm * 36 + c] = cvt_tf32(qh[c * 1024 + m0 + mm]);
    }

    // per-thread row constants (rows grp and grp+8 of this warp's strip)
    const int mg0 = m0 + w * 16 + grp;
    const int mg1 = mg0 + 8;
    const float cg00 = fmaf(((mg0 & 31) + 0.5f) * 0.0625f - 1.f, 15.5f, 31.f);
    const float cg01 = fmaf(((mg0 >> 5) + 0.5f) * 0.0625f - 1.f, 15.5f, 31.f);
    const float cg10 = fmaf(((mg1 & 31) + 0.5f) * 0.0625f - 1.f, 15.5f, 31.f);
    const float cg11 = fmaf(((mg1 >> 5) + 0.5f) * 0.0625f - 1.f, 15.5f, 31.f);

    const int rowA0 = (w * 16 + grp) * 36;
    const int rowA1 = rowA0 + 8 * 36;
    const int rowP0 = (w * 16 + grp) * 68;
    const int rowP1 = rowP0 + 8 * 68;

    float accv[4][4];
#pragma unroll
    for (int vf = 0; vf < 4; vf++)
#pragma unroll
        for (int j = 0; j < 4; j++) accv[vf][j] = 0.f;
    float L0 = 0.f, L1 = 0.f;

    const float scale = 0.17677669529663687f;   // 32^-0.5

    for (int nt = 0; nt < 16; nt++) {
        const int n0 = nt * 64;
        __syncthreads();
        // stage K, V (transposed, tf32) + pos
        for (int idx = tid; idx < 2048; idx += 256) {
            int c = idx >> 6, nn = idx & 63;
            sK[nn * 36 + c] = cvt_tf32(kh[c * 1024 + n0 + nn]);
            sV[nn * 36 + c] = cvt_tf32(vh[c * 1024 + n0 + nn]);
        }
        if (tid < 128) sPos[tid] = pos[bg * 2048 + n0 * 2 + tid];
        __syncthreads();

        // ---- QK: S[16x64] per warp, 8 n-frags x 4 k-steps
        float sc[8][4];
#pragma unroll
        for (int nf = 0; nf < 8; nf++)
#pragma unroll
            for (int j = 0; j < 4; j++) sc[nf][j] = 0.f;

#pragma unroll
        for (int kk = 0; kk < 4; kk++) {
            const int k0 = kk * 8;
            uint32_t a0 = sQ[rowA0 + k0 + tig];
            uint32_t a1 = sQ[rowA1 + k0 + tig];
            uint32_t a2 = sQ[rowA0 + k0 + tig + 4];
            uint32_t a3 = sQ[rowA1 + k0 + tig + 4];
#pragma unroll
            for (int nf = 0; nf < 8; nf++) {
                uint32_t b0 = sK[(nf * 8 + grp) * 36 + k0 + tig];
                uint32_t b1 = sK[(nf * 8 + grp) * 36 + k0 + tig + 4];
                mma_tf32(sc[nf], a0, a1, a2, a3, b0, b1);
            }
        }

        // ---- bias + exp (fp32), accumulate L, store P (tf32) to sP
#pragma unroll
        for (int nf = 0; nf < 8; nf++) {
            float4 pp = *(const float4*)&sPos[16 * nf + 4 * tig];
            float pb0 = 15.5f * pp.x, pb1 = 15.5f * pp.y;
            float pb2 = 15.5f * pp.z, pb3 = 15.5f * pp.w;
            float e0 = __expf(fmaf(sc[nf][0], scale, bias_T(sRpe, cg00 - pb0, cg01 - pb1)));
            float e1 = __expf(fmaf(sc[nf][1], scale, bias_T(sRpe, cg00 - pb2, cg01 - pb3)));
            float e2 = __expf(fmaf(sc[nf][2], scale, bias_T(sRpe, cg10 - pb0, cg11 - pb1)));
            float e3 = __expf(fmaf(sc[nf][3], scale, bias_T(sRpe, cg10 - pb2, cg11 - pb3)));
            L0 += e0 + e1;
            L1 += e2 + e3;
            uint2 lo = make_uint2(cvt_tf32(e0), cvt_tf32(e1));
            uint2 hi = make_uint2(cvt_tf32(e2), cvt_tf32(e3));
            *(uint2*)&sP[rowP0 + nf * 8 + 2 * tig] = lo;
            *(uint2*)&sP[rowP1 + nf * 8 + 2 * tig] = hi;
        }
        __syncwarp();

        // ---- PV: out[16x32] += P[16x64] * V^T ; 8 k-steps x 4 ch-frags
#pragma unroll
        for (int k8 = 0; k8 < 8; k8++) {
            const int kb = k8 * 8;
            uint32_t a0 = sP[rowP0 + kb + tig];
            uint32_t a1 = sP[rowP1 + kb + tig];
            uint32_t a2 = sP[rowP0 + kb + tig + 4];
            uint32_t a3 = sP[rowP1 + kb + tig + 4];
#pragma unroll
            for (int vf = 0; vf < 4; vf++) {
                uint32_t b0 = sV[(kb + tig) * 36 + vf * 8 + grp];
                uint32_t b1 = sV[(kb + tig + 4) * 36 + vf * 8 + grp];
                mma_tf32(accv[vf], a0, a1, a2, a3, b0, b1);
            }
        }
    }

    // reduce L across the quad (lanes sharing grp)
    L0 += __shfl_xor_sync(0xffffffffu, L0, 1);
    L0 += __shfl_xor_sync(0xffffffffu, L0, 2);
    L1 += __shfl_xor_sync(0xffffffffu, L1, 1);
    L1 += __shfl_xor_sync(0xffffffffu, L1, 2);
    const float rL0 = 1.f / L0;
    const float rL1 = 1.f / L1;

    // write: c0 (row grp, ch 2tig) c1 (+1 ch) c2 (row+8) c3
#pragma unroll
    for (int vf = 0; vf < 4; vf++) {
        int ch = h * 32 + vf * 8 + 2 * tig;
        int base = (b * 256 + ch) * 1024 + mg0;
        out[base]            = accv[vf][0] * rL0;
        out[base + 1024]     = accv[vf][1] * rL0;
        out[base + 8]        = accv[vf][2] * rL1;
        out[base + 1024 + 8] = accv[vf][3] * rL1;
    }
}

// ---------------- launch ----------------
extern "C" void kernel_launch(void* const* d_in, const int* in_sizes, int n_in,
                              void* d_out, int out_size)
{
    const float* x        = (const float*)d_in[0];
    const float* wq       = (const float*)d_in[1];
    const float* bq       = (const float*)d_in[2];
    const float* w_off_dw = (const float*)d_in[3];
    const float* b_off_dw = (const float*)d_in[4];
    const float* ln_g     = (const float*)d_in[5];
    const float* ln_b     = (const float*)d_in[6];
    const float* w_off_pj = (const float*)d_in[7];
    const float* wk       = (const float*)d_in[8];
    const float* bk       = (const float*)d_in[9];
    const float* wv       = (const float*)d_in[10];
    const float* bv       = (const float*)d_in[11];
    const float* wo       = (const float*)d_in[12];
    const float* bo       = (const float*)d_in[13];
    const float* rpe      = (const float*)d_in[14];
    float* out = (float*)d_out;

    float *qb, *xsb, *kb, *vb, *ob, *posb;
    cudaGetSymbolAddress((void**)&qb,   g_q);
    cudaGetSymbolAddress((void**)&xsb,  g_xs);
    cudaGetSymbolAddress((void**)&kb,   g_k);
    cudaGetSymbolAddress((void**)&vb,   g_v);
    cudaGetSymbolAddress((void**)&ob,   g_o);
    cudaGetSymbolAddress((void**)&posb, g_pos);

    const int attn_smem = 88576;   // 22144 words
    cudaFuncSetAttribute(attn_mma, cudaFuncAttributeMaxDynamicSharedMemorySize, attn_smem);
    const int off_smem = 163840;
    cudaFuncSetAttribute(offset_kernel, cudaFuncAttributeMaxDynamicSharedMemorySize, off_smem);

    const dim3 gg(16, 2, 4);

    gemm_conv<<<gg, 256>>>(wq, x, bq, qb);
    offset_kernel<<<64, 256, off_smem>>>(qb, w_off_dw, b_off_dw, ln_g, ln_b, w_off_pj,
                                         posb, out + 1048576, out + 1048576 + 32768);
    sample_kernel<<<64, 256>>>(x, posb, xsb);
    gemm_kv<<<dim3(16, 4, 4), 256>>>(wk, bk, kb, wv, bv, vb, xsb);
    attn_mma<<<dim3(8, 32), 256, attn_smem>>>(qb, kb, vb, rpe, posb, ob);
    gemm_conv<<<gg, 256>>>(wo, ob, bo, out);
}

// round 7
// speedup vs baseline: 1.6160x; 1.0316x over previous
#include <cuda_runtime.h>
#include <math.h>
#include <stdint.h>

// B=4, C=256, H=W=32, NH=8, HC=32, G=4, GC=64, ns=1024, KK=5, ORF=2
typedef unsigned long long u64;

__device__ __forceinline__ u64 fma2(u64 a, u64 b, u64 c) {
    u64 d;
    asm("fma.rn.f32x2 %0, %1, %2, %3;" : "=l"(d) : "l"(a), "l"(b), "l"(c));
    return d;
}
__device__ __forceinline__ u64 pack2(float lo, float hi) {
    u64 r;
    asm("mov.b64 %0, {%1, %2};" : "=l"(r) : "f"(lo), "f"(hi));
    return r;
}
__device__ __forceinline__ u64 dup2(float x) { return pack2(x, x); }
__device__ __forceinline__ void unpack2(u64 a, float& lo, float& hi) {
    asm("mov.b64 {%0, %1}, %2;" : "=f"(lo), "=f"(hi) : "l"(a));
}
__device__ __forceinline__ uint32_t cvt_tf32(float x) {
    uint32_t r;
    asm("cvt.rna.tf32.f32 %0, %1;" : "=r"(r) : "f"(x));
    return r;
}
__device__ __forceinline__ void mma_tf32(float c[4],
                                         uint32_t a0, uint32_t a1, uint32_t a2, uint32_t a3,
                                         uint32_t b0, uint32_t b1) {
    asm("mma.sync.aligned.m16n8k8.row.col.f32.tf32.tf32.f32 "
        "{%0,%1,%2,%3}, {%4,%5,%6,%7}, {%8,%9}, {%0,%1,%2,%3};"
        : "+f"(c[0]), "+f"(c[1]), "+f"(c[2]), "+f"(c[3])
        : "r"(a0), "r"(a1), "r"(a2), "r"(a3), "r"(b0), "r"(b1));
}

// ---------------- scratch ----------------
__device__ float g_q [4 * 256 * 1024];
__device__ float g_xs[4 * 256 * 1024];
__device__ float g_k [4 * 256 * 1024];
__device__ float g_v [4 * 256 * 1024];
__device__ float g_o [4 * 256 * 1024];
__device__ float g_pos[16 * 1024 * 2];

// ---------------- tf32 tensor-core SGEMM: Y[m,n] = W[m,k] X[k,n] + bias -----
// 128x64 tile, 8 warps in 4x2 (m x n), each warp 32x32, mma.m16n8k8.
__device__ __forceinline__ void gemm_tf32_body(const float* __restrict__ Wm,
                                               const float* __restrict__ Xb,
                                               const float* __restrict__ bias,
                                               float* __restrict__ Yb,
                                               int m0, int n0)
{
    __shared__ uint32_t As[4608];   // [128 m][32 k] stride 36
    __shared__ uint32_t Bs[2304];   // [64 n][32 k]  stride 36

    const int tid  = threadIdx.x;
    const int w    = tid >> 5;
    const int lane = tid & 31;
    const int grp  = lane >> 2;
    const int tig  = lane & 3;
    const int mw   = w >> 1;    // 0..3
    const int nw   = w & 1;     // 0..1

    float acc[2][4][4];
#pragma unroll
    for (int mf = 0; mf < 2; mf++)
#pragma unroll
        for (int nf = 0; nf < 4; nf++)
#pragma unroll
            for (int j = 0; j < 4; j++) acc[mf][nf][j] = 0.f;

    const int rowA0 = (mw * 32 + grp) * 36;
    const int rowB0 = (nw * 32 + grp) * 36;

    for (int k0 = 0; k0 < 256; k0 += 32) {
        __syncthreads();
        for (int idx = tid; idx < 4096; idx += 256) {
            int mm = idx >> 5, c = idx & 31;
            As[mm * 36 + c] = cvt_tf32(Wm[(m0 + mm) * 256 + k0 + c]);
        }
        for (int idx = tid; idx < 2048; idx += 256) {
            int c = idx >> 6, nn = idx & 63;
            Bs[nn * 36 + c] = cvt_tf32(Xb[(k0 + c) * 1024 + n0 + nn]);
        }
        __syncthreads();

#pragma unroll
        for (int kk = 0; kk < 4; kk++) {
            const int kb = kk * 8 + tig;
            uint32_t a00 = As[rowA0 + kb];
            uint32_t a01 = As[rowA0 + 288 + kb];
            uint32_t a02 = As[rowA0 + kb + 4];
            uint32_t a03 = As[rowA0 + 288 + kb + 4];
            uint32_t a10 = As[rowA0 + 576 + kb];
            uint32_t a11 = As[rowA0 + 864 + kb];
            uint32_t a12 = As[rowA0 + 576 + kb + 4];
            uint32_t a13 = As[rowA0 + 864 + kb + 4];
#pragma unroll
            for (int nf = 0; nf < 4; nf++) {
                uint32_t b0 = Bs[rowB0 + nf * 288 + kb];
                uint32_t b1 = Bs[rowB0 + nf * 288 + kb + 4];
                mma_tf32(acc[0][nf], a00, a01, a02, a03, b0, b1);
                mma_tf32(acc[1][nf], a10, a11, a12, a13, b0, b1);
            }
        }
    }

    const int mr0 = m0 + mw * 32 + grp;
#pragma unroll
    for (int mf = 0; mf < 2; mf++) {
        int r0 = mr0 + mf * 16;
        float b0 = bias[r0], b1 = bias[r0 + 8];
#pragma unroll
        for (int nf = 0; nf < 4; nf++) {
            int col = n0 + nw * 32 + nf * 8 + 2 * tig;
            float2 lo = make_float2(acc[mf][nf][0] + b0, acc[mf][nf][1] + b0);
            float2 hi = make_float2(acc[mf][nf][2] + b1, acc[mf][nf][3] + b1);
            *(float2*)&Yb[r0 * 1024 + col]       = lo;
            *(float2*)&Yb[(r0 + 8) * 1024 + col] = hi;
        }
    }
}

__global__ __launch_bounds__(256)
void gemm_q_tf32(const float* __restrict__ Wm, const float* __restrict__ X,
                 const float* __restrict__ bias, float* __restrict__ Y)
{
    gemm_tf32_body(Wm, X + blockIdx.z * 262144, bias, Y + blockIdx.z * 262144,
                   blockIdx.y * 128, blockIdx.x * 64);
}

__global__ __launch_bounds__(256)
void gemm_kv_tf32(const float* __restrict__ Wk, const float* __restrict__ bk,
                  float* __restrict__ Yk,
                  const float* __restrict__ Wv, const float* __restrict__ bv,
                  float* __restrict__ Yv, const float* __restrict__ X)
{
    const int my = blockIdx.y;
    const float* Xb = X + blockIdx.z * 262144;
    if (my < 2)
        gemm_tf32_body(Wk, Xb, bk, Yk + blockIdx.z * 262144, my * 128, blockIdx.x * 64);
    else
        gemm_tf32_body(Wv, Xb, bv, Yv + blockIdx.z * 262144, (my - 2) * 128, blockIdx.x * 64);
}

// ---------------- exact fp32 SGEMM (FFMA2) for the output projection --------
__global__ __launch_bounds__(256)
void gemm_conv(const float* __restrict__ Wm, const float* __restrict__ X,
               const float* __restrict__ bias, float* __restrict__ Y)
{
    const int b  = blockIdx.z;
    const int m0 = blockIdx.y * 128;
    const int n0 = blockIdx.x * 64;
    const float* Xb = X + b * 262144;
    float* Yb = Y + b * 262144;

    __shared__ float As[16][132];
    __shared__ float Bs[16][64];

    const int tid = threadIdx.x;
    const int tx = tid & 15;
    const int ty = tid >> 4;

    const int am = tid >> 1;
    const int ak = (tid & 1) * 8;
    const int bn = tid & 63;
    const int bk = (tid >> 6) * 4;

    u64 acc2[4][4];
#pragma unroll
    for (int p = 0; p < 4; p++)
#pragma unroll
        for (int j = 0; j < 4; j++) acc2[p][j] = 0ULL;

    float4 wa, wb;
    float  xr[4];
    {
        const float* wp = &Wm[(m0 + am) * 256 + ak];
        wa = *(const float4*)wp;
        wb = *(const float4*)(wp + 4);
#pragma unroll
        for (int u = 0; u < 4; u++) xr[u] = Xb[(bk + u) * 1024 + n0 + bn];
    }

    for (int k0 = 0; k0 < 256; k0 += 16) {
        As[ak + 0][am] = wa.x; As[ak + 1][am] = wa.y;
        As[ak + 2][am] = wa.z; As[ak + 3][am] = wa.w;
        As[ak + 4][am] = wb.x; As[ak + 5][am] = wb.y;
        As[ak + 6][am] = wb.z; As[ak + 7][am] = wb.w;
#pragma unroll
        for (int u = 0; u < 4; u++) Bs[bk + u][bn] = xr[u];
        __syncthreads();

        if (k0 + 16 < 256) {
            const float* wp = &Wm[(m0 + am) * 256 + k0 + 16 + ak];
            wa = *(const float4*)wp;
            wb = *(const float4*)(wp + 4);
#pragma unroll
            for (int u = 0; u < 4; u++)
                xr[u] = Xb[(k0 + 16 + bk + u) * 1024 + n0 + bn];
        }

#pragma unroll
        for (int kk = 0; kk < 16; kk++) {
            const u64* a2 = (const u64*)&As[kk][ty * 8];
            float4 b4 = *(const float4*)&Bs[kk][tx * 4];
            u64 bd[4] = {dup2(b4.x), dup2(b4.y), dup2(b4.z), dup2(b4.w)};
#pragma unroll
            for (int p = 0; p < 4; p++) {
                u64 av = a2[p];
#pragma unroll
                for (int j = 0; j < 4; j++)
                    acc2[p][j] = fma2(av, bd[j], acc2[p][j]);
            }
        }
        __syncthreads();
    }

#pragma unroll
    for (int p = 0; p < 4; p++) {
        float lo[4], hi[4];
#pragma unroll
        for (int j = 0; j < 4; j++) unpack2(acc2[p][j], lo[j], hi[j]);
        int r0 = m0 + ty * 8 + 2 * p;
        float b0 = bias[r0], b1 = bias[r0 + 1];
        float4 o0 = make_float4(lo[0] + b0, lo[1] + b0, lo[2] + b0, lo[3] + b0);
        float4 o1 = make_float4(hi[0] + b1, hi[1] + b1, hi[2] + b1, hi[3] + b1);
        *(float4*)&Yb[r0 * 1024 + n0 + tx * 4]       = o0;
        *(float4*)&Yb[(r0 + 1) * 1024 + n0 + tx * 4] = o1;
    }
}

// ---------------- offset pipeline: smem-staged conv, activations cached -----
__global__ __launch_bounds__(256)
void offset_kernel(const float* __restrict__ q, const float* __restrict__ w_dw,
                   const float* __restrict__ b_dw, const float* __restrict__ ln_g,
                   const float* __restrict__ ln_b, const float* __restrict__ wpj,
                   float* __restrict__ pos_buf, float* __restrict__ out_pos,
                   float* __restrict__ out_ref)
{
    extern __shared__ float dsm[];
    float* simg = dsm;               // [c][384]
    float* sa   = dsm + 64 * 384;    // [c][256]

    __shared__ float sw[1600];
    __shared__ float sb[64], sg[64], sbt[64], spj0[64], spj1[64];

    const int tid = threadIdx.x;
    for (int t = tid; t < 1600; t += 256) sw[t] = w_dw[t];
    if (tid < 64) {
        sb[tid] = b_dw[tid]; sg[tid] = ln_g[tid]; sbt[tid] = ln_b[tid];
        spj0[tid] = wpj[tid]; spj1[tid] = wpj[64 + tid];
    }

    const int bi = blockIdx.x;
    const int bg = bi >> 2;
    const int i0 = (bi & 3) * 8;
    const float* qb = q + bg * 65536;

    for (int t = tid; t < 24576; t += 256) {
        int c  = t / 384;
        int r2 = t - c * 384;
        int yy = i0 - 2 + (r2 >> 5);
        int col = r2 & 31;
        float vv = 0.f;
        if ((unsigned)yy < 32u) vv = qb[c * 1024 + yy * 32 + col];
        simg[c * 384 + r2] = vv;
    }
    __syncthreads();

    const int li = tid >> 5;
    const int j  = tid & 31;
    const int i  = i0 + li;

    float s1 = 0.f, s2 = 0.f;
    for (int c = 0; c < 64; c++) {
        const float* ic = simg + c * 384 + li * 32;
        const float* wc = sw + c * 25;
        float a = sb[c];
#pragma unroll
        for (int dy = 0; dy < 5; dy++) {
            const float* irow = ic + dy * 32;
#pragma unroll
            for (int dx = 0; dx < 5; dx++) {
                int xx = j + dx - 2;
                float vv = ((unsigned)xx < 32u) ? irow[xx] : 0.f;
                a = fmaf(vv, wc[dy * 5 + dx], a);
            }
        }
        s1 += a;
        s2 = fmaf(a, a, s2);
        sa[c * 256 + tid] = a;
    }
    float mu   = s1 * 0.015625f;
    float var  = s2 * 0.015625f - mu * mu;
    float rstd = rsqrtf(var + 1e-5f);

    float o0 = 0.f, o1 = 0.f;
    for (int c = 0; c < 64; c++) {
        float a  = sa[c * 256 + tid];
        float t2 = fmaf((a - mu) * rstd, sg[c], sbt[c]);
        float gl = 0.5f * t2 * (1.f + erff(t2 * 0.70710678118654752f));
        o0 = fmaf(gl, spj0[c], o0);
        o1 = fmaf(gl, spj1[c], o1);
    }
    float off0 = tanhf(o0) * 0.0625f;
    float off1 = tanhf(o1) * 0.0625f;
    float r0 = (j + 0.5f) * 0.0625f - 1.f;
    float r1 = (i + 0.5f) * 0.0625f - 1.f;
    float P0 = off0 + r0, P1 = off1 + r1;

    const int pix = bi * 256 + tid;
    pos_buf[pix * 2]     = P0;
    pos_buf[pix * 2 + 1] = P1;
    out_pos[pix * 2]     = P0;
    out_pos[pix * 2 + 1] = P1;
    out_ref[pix * 2]     = r0;
    out_ref[pix * 2 + 1] = r1;
}

// ---------------- bilinear sample of x at pos -> xs --------------------------
__global__ __launch_bounds__(256)
void sample_kernel(const float* __restrict__ x, const float* __restrict__ pos_buf,
                   float* __restrict__ xs)
{
    const int idx = blockIdx.x * 256 + threadIdx.x;
    const float P0 = pos_buf[idx * 2];
    const float P1 = pos_buf[idx * 2 + 1];
    const float gxp = (P1 + 1.f) * 15.5f;
    const float gyp = (P0 + 1.f) * 15.5f;
    float x0f = floorf(gxp), y0f = floorf(gyp);
    float x1f = x0f + 1.f,  y1f = y0f + 1.f;
    float wx1 = gxp - x0f, wx0 = 1.f - wx1;
    float wy1 = gyp - y0f, wy0 = 1.f - wy1;
    bool vx0 = (x0f >= 0.f) && (x0f <= 31.f);
    bool vx1 = (x1f >= 0.f) && (x1f <= 31.f);
    bool vy0 = (y0f >= 0.f) && (y0f <= 31.f);
    bool vy1 = (y1f >= 0.f) && (y1f <= 31.f);
    int X0 = (int)fminf(fmaxf(x0f, 0.f), 31.f);
    int X1 = (int)fminf(fmaxf(x1f, 0.f), 31.f);
    int Y0 = (int)fminf(fmaxf(y0f, 0.f), 31.f);
    int Y1 = (int)fminf(fmaxf(y1f, 0.f), 31.f);
    float w00 = (vy0 && vx0) ? wy0 * wx0 : 0.f;
    float w01 = (vy0 && vx1) ? wy0 * wx1 : 0.f;
    float w10 = (vy1 && vx0) ? wy1 * wx0 : 0.f;
    float w11 = (vy1 && vx1) ? wy1 * wx1 : 0.f;
    int i00 = Y0 * 32 + X0, i01 = Y0 * 32 + X1;
    int i10 = Y1 * 32 + X0, i11 = Y1 * 32 + X1;

    const int bg = idx >> 10, n = idx & 1023;
    const float* xb = x + bg * 65536;
    float* xo = xs + bg * 65536 + n;
    for (int c = 0; c < 64; c++) {
        const float* xc = xb + c * 1024;
        float vout = w00 * xc[i00] + w01 * xc[i01] + w10 * xc[i10] + w11 * xc[i11];
        xo[c * 1024] = vout;
    }
}

// ---------------- RPE bilinear from PAIRED table: sR2[ix][iy]=(T[iy][ix],T[iy+1][ix])
__device__ __forceinline__ float bias_P(const float2* __restrict__ sR2,
                                        float gyp, float gxp)
{
    float yf = floorf(gyp), xf = floorf(gxp);
    int yi = (int)yf, xi = (int)xf;
    float wy1 = gyp - yf, wx1 = gxp - xf;
    float2 p0 = sR2[(xi << 6) + yi];
    float2 p1 = sR2[(xi << 6) + 64 + yi];
    float v0 = fmaf(wy1, p0.y - p0.x, p0.x);
    float v1 = fmaf(wy1, p1.y - p1.x, p1.x);
    return fmaf(wx1, v1 - v0, v0);
}

// ---------------- fused attention on tensor cores (mma.sync tf32) ------------
// grid (8, 32): m-tile 128, 8 warps. smem 104960 B, occ 2.
__global__ __launch_bounds__(256, 2)
void attn_mma(const float* __restrict__ q, const float* __restrict__ k,
              const float* __restrict__ v, const float* __restrict__ rpe,
              const float* __restrict__ pos, float* __restrict__ out)
{
    extern __shared__ float smf[];
    uint32_t* sQ  = (uint32_t*)smf;          // [m=128][c=32] stride 36 : 4608
    uint32_t* sK  = sQ + 4608;               // [n=64][c=32]  stride 36 : 2304
    uint32_t* sV  = sK + 2304;               // [s=64][ch=32] stride 36 : 2304
    uint32_t* sP  = sV + 2304;               // [m=128][s=64] stride 68 : 8704
    float*  sPos  = (float*)(sP + 8704);     // 128
    float2* sR2   = (float2*)(sPos + 128);   // 4096 float2 (paired rpe)

    const int bh = blockIdx.y;
    const int b  = bh >> 3, h = bh & 7;
    const int gq = h >> 1;
    const int bg = b * 4 + gq;
    const int m0 = blockIdx.x * 128;
    const float* rpe_h = rpe + h * 3969;

    const int tid  = threadIdx.x;
    const int w    = tid >> 5;
    const int lane = tid & 31;
    const int grp  = lane >> 2;
    const int tig  = lane & 3;

    // paired RPE table: sR2[x*64+y] = (T[y][x], T[y+1][x]); zero padding
    for (int t = tid; t < 4096; t += 256) sR2[t] = make_float2(0.f, 0.f);
    __syncthreads();
    for (int t = tid; t < 3969; t += 256) {
        int r = t / 63, c2 = t - r * 63;
        float val = rpe_h[t];
        sR2[(c2 << 6) + r].x = val;
        if (r > 0) sR2[(c2 << 6) + r - 1].y = val;
    }

    const float* qh = q + (b * 256 + h * 32) * 1024;
    const float* kh = k + (b * 256 + h * 32) * 1024;
    const float* vh = v + (b * 256 + h * 32) * 1024;

    for (int idx = tid; idx < 4096; idx += 256) {
        int c = idx >> 7, mm = idx & 127;
        sQ[mm * 36 + c] = cvt_tf32(qh[c * 1024 + m0 + mm]);
    }

    const int mg0 = m0 + w * 16 + grp;
    const int mg1 = mg0 + 8;
    const float cg00 = fmaf(((mg0 & 31) + 0.5f) * 0.0625f - 1.f, 15.5f, 31.f);
    const float cg01 = fmaf(((mg0 >> 5) + 0.5f) * 0.0625f - 1.f, 15.5f, 31.f);
    const float cg10 = fmaf(((mg1 & 31) + 0.5f) * 0.0625f - 1.f, 15.5f, 31.f);
    const float cg11 = fmaf(((mg1 >> 5) + 0.5f) * 0.0625f - 1.f, 15.5f, 31.f);

    const int rowA0 = (w * 16 + grp) * 36;
    const int rowA1 = rowA0 + 8 * 36;
    const int rowP0 = (w * 16 + grp) * 68;
    const int rowP1 = rowP0 + 8 * 68;

    float accv[4][4];
#pragma unroll
    for (int vf = 0; vf < 4; vf++)
#pragma unroll
        for (int j = 0; j < 4; j++) accv[vf][j] = 0.f;
    float L0 = 0.f, L1 = 0.f;

    const float scale = 0.17677669529663687f;

    for (int nt = 0; nt < 16; nt++) {
        const int n0 = nt * 64;
        __syncthreads();
        for (int idx = tid; idx < 2048; idx += 256) {
            int c = idx >> 6, nn = idx & 63;
            sK[nn * 36 + c] = cvt_tf32(kh[c * 1024 + n0 + nn]);
            sV[nn * 36 + c] = cvt_tf32(vh[c * 1024 + n0 + nn]);
        }
        if (tid < 128) sPos[tid] = pos[bg * 2048 + n0 * 2 + tid];
        __syncthreads();

        // ---- QK
        float sc[8][4];
#pragma unroll
        for (int nf = 0; nf < 8; nf++)
#pragma unroll
            for (int j = 0; j < 4; j++) sc[nf][j] = 0.f;

#pragma unroll
        for (int kk = 0; kk < 4; kk++) {
            const int k0 = kk * 8;
            uint32_t a0 = sQ[rowA0 + k0 + tig];
            uint32_t a1 = sQ[rowA1 + k0 + tig];
            uint32_t a2 = sQ[rowA0 + k0 + tig + 4];
            uint32_t a3 = sQ[rowA1 + k0 + tig + 4];
#pragma unroll
            for (int nf = 0; nf < 8; nf++) {
                uint32_t b0 = sK[(nf * 8 + grp) * 36 + k0 + tig];
                uint32_t b1 = sK[(nf * 8 + grp) * 36 + k0 + tig + 4];
                mma_tf32(sc[nf], a0, a1, a2, a3, b0, b1);
            }
        }

        // ---- bias + exp, accumulate L, store P (tf32)
#pragma unroll
        for (int nf = 0; nf < 8; nf++) {
            float4 pp = *(const float4*)&sPos[16 * nf + 4 * tig];
            float pb0 = 15.5f * pp.x, pb1 = 15.5f * pp.y;
            float pb2 = 15.5f * pp.z, pb3 = 15.5f * pp.w;
            float e0 = __expf(fmaf(sc[nf][0], scale, bias_P(sR2, cg00 - pb0, cg01 - pb1)));
            float e1 = __expf(fmaf(sc[nf][1], scale, bias_P(sR2, cg00 - pb2, cg01 - pb3)));
            float e2 = __expf(fmaf(sc[nf][2], scale, bias_P(sR2, cg10 - pb0, cg11 - pb1)));
            float e3 = __expf(fmaf(sc[nf][3], scale, bias_P(sR2, cg10 - pb2, cg11 - pb3)));
            L0 += e0 + e1;
            L1 += e2 + e3;
            uint2 lo = make_uint2(cvt_tf32(e0), cvt_tf32(e1));
            uint2 hi = make_uint2(cvt_tf32(e2), cvt_tf32(e3));
            *(uint2*)&sP[rowP0 + nf * 8 + 2 * tig] = lo;
            *(uint2*)&sP[rowP1 + nf * 8 + 2 * tig] = hi;
        }
        __syncwarp();

        // ---- PV
#pragma unroll
        for (int k8 = 0; k8 < 8; k8++) {
            const int kb = k8 * 8;
            uint32_t a0 = sP[rowP0 + kb + tig];
            uint32_t a1 = sP[rowP1 + kb + tig];
            uint32_t a2 = sP[rowP0 + kb + tig + 4];
            uint32_t a3 = sP[rowP1 + kb + tig + 4];
#pragma unroll
            for (int vf = 0; vf < 4; vf++) {
                uint32_t b0 = sV[(kb + tig) * 36 + vf * 8 + grp];
                uint32_t b1 = sV[(kb + tig + 4) * 36 + vf * 8 + grp];
                mma_tf32(accv[vf], a0, a1, a2, a3, b0, b1);
            }
        }
    }

    L0 += __shfl_xor_sync(0xffffffffu, L0, 1);
    L0 += __shfl_xor_sync(0xffffffffu, L0, 2);
    L1 += __shfl_xor_sync(0xffffffffu, L1, 1);
    L1 += __shfl_xor_sync(0xffffffffu, L1, 2);
    const float rL0 = 1.f / L0;
    const float rL1 = 1.f / L1;

#pragma unroll
    for (int vf = 0; vf < 4; vf++) {
        int ch = h * 32 + vf * 8 + 2 * tig;
        int base = (b * 256 + ch) * 1024 + mg0;
        out[base]            = accv[vf][0] * rL0;
        out[base + 1024]     = accv[vf][1] * rL0;
        out[base + 8]        = accv[vf][2] * rL1;
        out[base + 1024 + 8] = accv[vf][3] * rL1;
    }
}

// ---------------- launch ----------------
extern "C" void kernel_launch(void* const* d_in, const int* in_sizes, int n_in,
                              void* d_out, int out_size)
{
    const float* x        = (const float*)d_in[0];
    const float* wq       = (const float*)d_in[1];
    const float* bq       = (const float*)d_in[2];
    const float* w_off_dw = (const float*)d_in[3];
    const float* b_off_dw = (const float*)d_in[4];
    const float* ln_g     = (const float*)d_in[5];
    const float* ln_b     = (const float*)d_in[6];
    const float* w_off_pj = (const float*)d_in[7];
    const float* wk       = (const float*)d_in[8];
    const float* bk       = (const float*)d_in[9];
    const float* wv       = (const float*)d_in[10];
    const float* bv       = (const float*)d_in[11];
    const float* wo       = (const float*)d_in[12];
    const float* bo       = (const float*)d_in[13];
    const float* rpe      = (const float*)d_in[14];
    float* out = (float*)d_out;

    float *qb, *xsb, *kb, *vb, *ob, *posb;
    cudaGetSymbolAddress((void**)&qb,   g_q);
    cudaGetSymbolAddress((void**)&xsb,  g_xs);
    cudaGetSymbolAddress((void**)&kb,   g_k);
    cudaGetSymbolAddress((void**)&vb,   g_v);
    cudaGetSymbolAddress((void**)&ob,   g_o);
    cudaGetSymbolAddress((void**)&posb, g_pos);

    const int attn_smem = 104960;   // 18048 words + 4096 float2
    cudaFuncSetAttribute(attn_mma, cudaFuncAttributeMaxDynamicSharedMemorySize, attn_smem);
    const int off_smem = 163840;
    cudaFuncSetAttribute(offset_kernel, cudaFuncAttributeMaxDynamicSharedMemorySize, off_smem);

    const dim3 gg(16, 2, 4);

    gemm_q_tf32<<<gg, 256>>>(wq, x, bq, qb);
    offset_kernel<<<64, 256, off_smem>>>(qb, w_off_dw, b_off_dw, ln_g, ln_b, w_off_pj,
                                         posb, out + 1048576, out + 1048576 + 32768);
    sample_kernel<<<64, 256>>>(x, posb, xsb);
    gemm_kv_tf32<<<dim3(16, 4, 4), 256>>>(wk, bk, kb, wv, bv, vb, xsb);
    attn_mma<<<dim3(8, 32), 256, attn_smem>>>(qb, kb, vb, rpe, posb, ob);
    gemm_conv<<<gg, 256>>>(wo, ob, bo, out);
}

// round 8
// speedup vs baseline: 1.9117x; 1.1830x over previous
#include <cuda_runtime.h>
#include <math.h>
#include <stdint.h>

// B=4, C=256, H=W=32, NH=8, HC=32, G=4, GC=64, ns=1024, KK=5, ORF=2
typedef unsigned long long u64;

__device__ __forceinline__ u64 fma2(u64 a, u64 b, u64 c) {
    u64 d;
    asm("fma.rn.f32x2 %0, %1, %2, %3;" : "=l"(d) : "l"(a), "l"(b), "l"(c));
    return d;
}
__device__ __forceinline__ u64 pack2(float lo, float hi) {
    u64 r;
    asm("mov.b64 %0, {%1, %2};" : "=l"(r) : "f"(lo), "f"(hi));
    return r;
}
__device__ __forceinline__ u64 dup2(float x) { return pack2(x, x); }
__device__ __forceinline__ void unpack2(u64 a, float& lo, float& hi) {
    asm("mov.b64 {%0, %1}, %2;" : "=f"(lo), "=f"(hi) : "l"(a));
}
__device__ __forceinline__ uint32_t cvt_tf32(float x) {
    uint32_t r;
    asm("cvt.rna.tf32.f32 %0, %1;" : "=r"(r) : "f"(x));
    return r;
}
__device__ __forceinline__ void mma_tf32(float c[4],
                                         uint32_t a0, uint32_t a1, uint32_t a2, uint32_t a3,
                                         uint32_t b0, uint32_t b1) {
    asm("mma.sync.aligned.m16n8k8.row.col.f32.tf32.tf32.f32 "
        "{%0,%1,%2,%3}, {%4,%5,%6,%7}, {%8,%9}, {%0,%1,%2,%3};"
        : "+f"(c[0]), "+f"(c[1]), "+f"(c[2]), "+f"(c[3])
        : "r"(a0), "r"(a1), "r"(a2), "r"(a3), "r"(b0), "r"(b1));
}

// ---------------- scratch ----------------
__device__ float g_q [4 * 256 * 1024];
__device__ float g_xs[4 * 256 * 1024];
__device__ float g_k [4 * 256 * 1024];
__device__ float g_v [4 * 256 * 1024];
__device__ float g_o [4 * 256 * 1024];
__device__ float g_pos[16 * 1024 * 2];

// ---------------- tf32 tensor-core SGEMM, double-buffered -------------------
// 128x64 tile, 8 warps (4x2), warp 32x32, mma.m16n8k8, 1 sync per k-chunk.
// dynamic smem: 2 * (4608 + 2304) u32 = 55296 B
__device__ __forceinline__ void gemm_tf32_body(const float* __restrict__ Wm,
                                               const float* __restrict__ Xb,
                                               const float* __restrict__ bias,
                                               float* __restrict__ Yb,
                                               int m0, int n0, uint32_t* sm)
{
    uint32_t* As = sm;           // [2][128 m][32 k] stride 36
    uint32_t* Bs = sm + 9216;    // [2][64 n][32 k]  stride 36

    const int tid  = threadIdx.x;
    const int w    = tid >> 5;
    const int lane = tid & 31;
    const int grp  = lane >> 2;
    const int tig  = lane & 3;
    const int mw   = w >> 1;
    const int nw   = w & 1;

    // staging indices (per-thread constants)
    const int a_m = tid >> 5;     // + t*8
    const int a_c = tid & 31;
    const int b_c = tid >> 6;     // + t*4
    const int b_n = tid & 63;

    float acc[2][4][4];
#pragma unroll
    for (int mf = 0; mf < 2; mf++)
#pragma unroll
        for (int nf = 0; nf < 4; nf++)
#pragma unroll
            for (int j = 0; j < 4; j++) acc[mf][nf][j] = 0.f;

    const int rowA0 = (mw * 32 + grp) * 36;
    const int rowB0 = (nw * 32 + grp) * 36;

    float wr[16], xr[8];
#pragma unroll
    for (int t = 0; t < 16; t++)
        wr[t] = Wm[(m0 + t * 8 + a_m) * 256 + a_c];
#pragma unroll
    for (int t = 0; t < 8; t++)
        xr[t] = Xb[(t * 4 + b_c) * 1024 + n0 + b_n];

    for (int kc = 0; kc < 8; kc++) {
        uint32_t* As_b = As + (kc & 1) * 4608;
        uint32_t* Bs_b = Bs + (kc & 1) * 2304;
#pragma unroll
        for (int t = 0; t < 16; t++)
            As_b[(t * 8 + a_m) * 36 + a_c] = cvt_tf32(wr[t]);
#pragma unroll
        for (int t = 0; t < 8; t++)
            Bs_b[b_n * 36 + t * 4 + b_c] = cvt_tf32(xr[t]);
        __syncthreads();

        if (kc < 7) {
            const int k0 = (kc + 1) * 32;
#pragma unroll
            for (int t = 0; t < 16; t++)
                wr[t] = Wm[(m0 + t * 8 + a_m) * 256 + k0 + a_c];
#pragma unroll
            for (int t = 0; t < 8; t++)
                xr[t] = Xb[(k0 + t * 4 + b_c) * 1024 + n0 + b_n];
        }

#pragma unroll
        for (int kk = 0; kk < 4; kk++) {
            const int kb = kk * 8 + tig;
            uint32_t a00 = As_b[rowA0 + kb];
            uint32_t a01 = As_b[rowA0 + 288 + kb];
            uint32_t a02 = As_b[rowA0 + kb + 4];
            uint32_t a03 = As_b[rowA0 + 288 + kb + 4];
            uint32_t a10 = As_b[rowA0 + 576 + kb];
            uint32_t a11 = As_b[rowA0 + 864 + kb];
            uint32_t a12 = As_b[rowA0 + 576 + kb + 4];
            uint32_t a13 = As_b[rowA0 + 864 + kb + 4];
#pragma unroll
            for (int nf = 0; nf < 4; nf++) {
                uint32_t b0 = Bs_b[rowB0 + nf * 288 + kb];
                uint32_t b1 = Bs_b[rowB0 + nf * 288 + kb + 4];
                mma_tf32(acc[0][nf], a00, a01, a02, a03, b0, b1);
                mma_tf32(acc[1][nf], a10, a11, a12, a13, b0, b1);
            }
        }
    }

    const int mr0 = m0 + mw * 32 + grp;
#pragma unroll
    for (int mf = 0; mf < 2; mf++) {
        int r0 = mr0 + mf * 16;
        float b0 = bias[r0], b1 = bias[r0 + 8];
#pragma unroll
        for (int nf = 0; nf < 4; nf++) {
            int col = n0 + nw * 32 + nf * 8 + 2 * tig;
            float2 lo = make_float2(acc[mf][nf][0] + b0, acc[mf][nf][1] + b0);
            float2 hi = make_float2(acc[mf][nf][2] + b1, acc[mf][nf][3] + b1);
            *(float2*)&Yb[r0 * 1024 + col]       = lo;
            *(float2*)&Yb[(r0 + 8) * 1024 + col] = hi;
        }
    }
}

__global__ __launch_bounds__(256, 3)
void gemm_q_tf32(const float* __restrict__ Wm, const float* __restrict__ X,
                 const float* __restrict__ bias, float* __restrict__ Y)
{
    extern __shared__ uint32_t smq[];
    gemm_tf32_body(Wm, X + blockIdx.z * 262144, bias, Y + blockIdx.z * 262144,
                   blockIdx.y * 128, blockIdx.x * 64, smq);
}

__global__ __launch_bounds__(256, 3)
void gemm_kv_tf32(const float* __restrict__ Wk, const float* __restrict__ bk,
                  float* __restrict__ Yk,
                  const float* __restrict__ Wv, const float* __restrict__ bv,
                  float* __restrict__ Yv, const float* __restrict__ X)
{
    extern __shared__ uint32_t smkv[];
    const int my = blockIdx.y;
    const float* Xb = X + blockIdx.z * 262144;
    if (my < 2)
        gemm_tf32_body(Wk, Xb, bk, Yk + blockIdx.z * 262144, my * 128, blockIdx.x * 64, smkv);
    else
        gemm_tf32_body(Wv, Xb, bv, Yv + blockIdx.z * 262144, (my - 2) * 128, blockIdx.x * 64, smkv);
}

// ---------------- exact fp32 SGEMM (FFMA2) for the output projection --------
__global__ __launch_bounds__(256)
void gemm_conv(const float* __restrict__ Wm, const float* __restrict__ X,
               const float* __restrict__ bias, float* __restrict__ Y)
{
    const int b  = blockIdx.z;
    const int m0 = blockIdx.y * 128;
    const int n0 = blockIdx.x * 64;
    const float* Xb = X + b * 262144;
    float* Yb = Y + b * 262144;

    __shared__ float As[16][132];
    __shared__ float Bs[16][64];

    const int tid = threadIdx.x;
    const int tx = tid & 15;
    const int ty = tid >> 4;

    const int am = tid >> 1;
    const int ak = (tid & 1) * 8;
    const int bn = tid & 63;
    const int bk = (tid >> 6) * 4;

    u64 acc2[4][4];
#pragma unroll
    for (int p = 0; p < 4; p++)
#pragma unroll
        for (int j = 0; j < 4; j++) acc2[p][j] = 0ULL;

    float4 wa, wb;
    float  xr[4];
    {
        const float* wp = &Wm[(m0 + am) * 256 + ak];
        wa = *(const float4*)wp;
        wb = *(const float4*)(wp + 4);
#pragma unroll
        for (int u = 0; u < 4; u++) xr[u] = Xb[(bk + u) * 1024 + n0 + bn];
    }

    for (int k0 = 0; k0 < 256; k0 += 16) {
        As[ak + 0][am] = wa.x; As[ak + 1][am] = wa.y;
        As[ak + 2][am] = wa.z; As[ak + 3][am] = wa.w;
        As[ak + 4][am] = wb.x; As[ak + 5][am] = wb.y;
        As[ak + 6][am] = wb.z; As[ak + 7][am] = wb.w;
#pragma unroll
        for (int u = 0; u < 4; u++) Bs[bk + u][bn] = xr[u];
        __syncthreads();

        if (k0 + 16 < 256) {
            const float* wp = &Wm[(m0 + am) * 256 + k0 + 16 + ak];
            wa = *(const float4*)wp;
            wb = *(const float4*)(wp + 4);
#pragma unroll
            for (int u = 0; u < 4; u++)
                xr[u] = Xb[(k0 + 16 + bk + u) * 1024 + n0 + bn];
        }

#pragma unroll
        for (int kk = 0; kk < 16; kk++) {
            const u64* a2 = (const u64*)&As[kk][ty * 8];
            float4 b4 = *(const float4*)&Bs[kk][tx * 4];
            u64 bd[4] = {dup2(b4.x), dup2(b4.y), dup2(b4.z), dup2(b4.w)};
#pragma unroll
            for (int p = 0; p < 4; p++) {
                u64 av = a2[p];
#pragma unroll
                for (int j = 0; j < 4; j++)
                    acc2[p][j] = fma2(av, bd[j], acc2[p][j]);
            }
        }
        __syncthreads();
    }

#pragma unroll
    for (int p = 0; p < 4; p++) {
        float lo[4], hi[4];
#pragma unroll
        for (int j = 0; j < 4; j++) unpack2(acc2[p][j], lo[j], hi[j]);
        int r0 = m0 + ty * 8 + 2 * p;
        float b0 = bias[r0], b1 = bias[r0 + 1];
        float4 o0 = make_float4(lo[0] + b0, lo[1] + b0, lo[2] + b0, lo[3] + b0);
        float4 o1 = make_float4(hi[0] + b1, hi[1] + b1, hi[2] + b1, hi[3] + b1);
        *(float4*)&Yb[r0 * 1024 + n0 + tx * 4]       = o0;
        *(float4*)&Yb[(r0 + 1) * 1024 + n0 + tx * 4] = o1;
    }
}

// ---------------- offset pipeline: smem-staged conv, activations cached -----
__global__ __launch_bounds__(256)
void offset_kernel(const float* __restrict__ q, const float* __restrict__ w_dw,
                   const float* __restrict__ b_dw, const float* __restrict__ ln_g,
                   const float* __restrict__ ln_b, const float* __restrict__ wpj,
                   float* __restrict__ pos_buf, float* __restrict__ out_pos,
                   float* __restrict__ out_ref)
{
    extern __shared__ float dsm[];
    float* simg = dsm;               // [c][384]
    float* sa   = dsm + 64 * 384;    // [c][256]

    __shared__ float sw[1600];
    __shared__ float sb[64], sg[64], sbt[64], spj0[64], spj1[64];

    const int tid = threadIdx.x;
    for (int t = tid; t < 1600; t += 256) sw[t] = w_dw[t];
    if (tid < 64) {
        sb[tid] = b_dw[tid]; sg[tid] = ln_g[tid]; sbt[tid] = ln_b[tid];
        spj0[tid] = wpj[tid]; spj1[tid] = wpj[64 + tid];
    }

    const int bi = blockIdx.x;
    const int bg = bi >> 2;
    const int i0 = (bi & 3) * 8;
    const float* qb = q + bg * 65536;

    for (int t = tid; t < 24576; t += 256) {
        int c  = t / 384;
        int r2 = t - c * 384;
        int yy = i0 - 2 + (r2 >> 5);
        int col = r2 & 31;
        float vv = 0.f;
        if ((unsigned)yy < 32u) vv = qb[c * 1024 + yy * 32 + col];
        simg[c * 384 + r2] = vv;
    }
    __syncthreads();

    const int li = tid >> 5;
    const int j  = tid & 31;
    const int i  = i0 + li;

    float s1 = 0.f, s2 = 0.f;
    for (int c = 0; c < 64; c++) {
        const float* ic = simg + c * 384 + li * 32;
        const float* wc = sw + c * 25;
        float a = sb[c];
#pragma unroll
        for (int dy = 0; dy < 5; dy++) {
            const float* irow = ic + dy * 32;
#pragma unroll
            for (int dx = 0; dx < 5; dx++) {
                int xx = j + dx - 2;
                float vv = ((unsigned)xx < 32u) ? irow[xx] : 0.f;
                a = fmaf(vv, wc[dy * 5 + dx], a);
            }
        }
        s1 += a;
        s2 = fmaf(a, a, s2);
        sa[c * 256 + tid] = a;
    }
    float mu   = s1 * 0.015625f;
    float var  = s2 * 0.015625f - mu * mu;
    float rstd = rsqrtf(var + 1e-5f);

    float o0 = 0.f, o1 = 0.f;
    for (int c = 0; c < 64; c++) {
        float a  = sa[c * 256 + tid];
        float t2 = fmaf((a - mu) * rstd, sg[c], sbt[c]);
        float gl = 0.5f * t2 * (1.f + erff(t2 * 0.70710678118654752f));
        o0 = fmaf(gl, spj0[c], o0);
        o1 = fmaf(gl, spj1[c], o1);
    }
    float off0 = tanhf(o0) * 0.0625f;
    float off1 = tanhf(o1) * 0.0625f;
    float r0 = (j + 0.5f) * 0.0625f - 1.f;
    float r1 = (i + 0.5f) * 0.0625f - 1.f;
    float P0 = off0 + r0, P1 = off1 + r1;

    const int pix = bi * 256 + tid;
    pos_buf[pix * 2]     = P0;
    pos_buf[pix * 2 + 1] = P1;
    out_pos[pix * 2]     = P0;
    out_pos[pix * 2 + 1] = P1;
    out_ref[pix * 2]     = r0;
    out_ref[pix * 2 + 1] = r1;
}

// ---------------- bilinear sample of x at pos -> xs --------------------------
__global__ __launch_bounds__(256)
void sample_kernel(const float* __restrict__ x, const float* __restrict__ pos_buf,
                   float* __restrict__ xs)
{
    const int idx = blockIdx.x * 256 + threadIdx.x;
    const float P0 = pos_buf[idx * 2];
    const float P1 = pos_buf[idx * 2 + 1];
    const float gxp = (P1 + 1.f) * 15.5f;
    const float gyp = (P0 + 1.f) * 15.5f;
    float x0f = floorf(gxp), y0f = floorf(gyp);
    float x1f = x0f + 1.f,  y1f = y0f + 1.f;
    float wx1 = gxp - x0f, wx0 = 1.f - wx1;
    float wy1 = gyp - y0f, wy0 = 1.f - wy1;
    bool vx0 = (x0f >= 0.f) && (x0f <= 31.f);
    bool vx1 = (x1f >= 0.f) && (x1f <= 31.f);
    bool vy0 = (y0f >= 0.f) && (y0f <= 31.f);
    bool vy1 = (y1f >= 0.f) && (y1f <= 31.f);
    int X0 = (int)fminf(fmaxf(x0f, 0.f), 31.f);
    int X1 = (int)fminf(fmaxf(x1f, 0.f), 31.f);
    int Y0 = (int)fminf(fmaxf(y0f, 0.f), 31.f);
    int Y1 = (int)fminf(fmaxf(y1f, 0.f), 31.f);
    float w00 = (vy0 && vx0) ? wy0 * wx0 : 0.f;
    float w01 = (vy0 && vx1) ? wy0 * wx1 : 0.f;
    float w10 = (vy1 && vx0) ? wy1 * wx0 : 0.f;
    float w11 = (vy1 && vx1) ? wy1 * wx1 : 0.f;
    int i00 = Y0 * 32 + X0, i01 = Y0 * 32 + X1;
    int i10 = Y1 * 32 + X0, i11 = Y1 * 32 + X1;

    const int bg = idx >> 10, n = idx & 1023;
    const float* xb = x + bg * 65536;
    float* xo = xs + bg * 65536 + n;
    for (int c = 0; c < 64; c++) {
        const float* xc = xb + c * 1024;
        float vout = w00 * xc[i00] + w01 * xc[i01] + w10 * xc[i10] + w11 * xc[i11];
        xo[c * 1024] = vout;
    }
}

// ---------------- RPE bilinear from PAIRED table: sR2[ix][iy]=(T[iy][ix],T[iy+1][ix])
__device__ __forceinline__ float bias_P(const float2* __restrict__ sR2,
                                        float gyp, float gxp)
{
    float yf = floorf(gyp), xf = floorf(gxp);
    int yi = (int)yf, xi = (int)xf;
    float wy1 = gyp - yf, wx1 = gxp - xf;
    float2 p0 = sR2[(xi << 6) + yi];
    float2 p1 = sR2[(xi << 6) + 64 + yi];
    float v0 = fmaf(wy1, p0.y - p0.x, p0.x);
    float v1 = fmaf(wy1, p1.y - p1.x, p1.x);
    return fmaf(wx1, v1 - v0, v0);
}

// ---------------- fused attention on tensor cores, register-resident P -------
// QK's B rows are fed permuted (perm(g) = g&1 ? g/2+4 : g/2) so the C fragment
// holds scores for samples {tig, tig+4} — exactly the A-fragment layout the PV
// mma needs. P never touches smem. smem 70144 B, occ 3.
__global__ __launch_bounds__(256, 3)
void attn_mma(const float* __restrict__ q, const float* __restrict__ k,
              const float* __restrict__ v, const float* __restrict__ rpe,
              const float* __restrict__ pos, float* __restrict__ out)
{
    extern __shared__ float smf[];
    uint32_t* sQ  = (uint32_t*)smf;          // [m=128][c=32] stride 36 : 4608
    uint32_t* sK  = sQ + 4608;               // [n=64][c=32]  stride 36 : 2304
    uint32_t* sV  = sK + 2304;               // [s=64][ch=32] stride 36 : 2304
    float*  sPos  = (float*)(sV + 2304);     // 128
    float2* sR2   = (float2*)(sPos + 128);   // 4096 float2

    const int bh = blockIdx.y;
    const int b  = bh >> 3, h = bh & 7;
    const int gq = h >> 1;
    const int bg = b * 4 + gq;
    const int m0 = blockIdx.x * 128;
    const float* rpe_h = rpe + h * 3969;

    const int tid  = threadIdx.x;
    const int w    = tid >> 5;
    const int lane = tid & 31;
    const int grp  = lane >> 2;
    const int tig  = lane & 3;
    const int pgrp = (grp & 1) ? (grp >> 1) + 4 : (grp >> 1);  // B-row permutation

    for (int t = tid; t < 4096; t += 256) sR2[t] = make_float2(0.f, 0.f);
    __syncthreads();
    for (int t = tid; t < 3969; t += 256) {
        int r = t / 63, c2 = t - r * 63;
        float val = rpe_h[t];
        sR2[(c2 << 6) + r].x = val;
        if (r > 0) sR2[(c2 << 6) + r - 1].y = val;
    }

    const float* qh = q + (b * 256 + h * 32) * 1024;
    const float* kh = k + (b * 256 + h * 32) * 1024;
    const float* vh = v + (b * 256 + h * 32) * 1024;

    for (int idx = tid; idx < 4096; idx += 256) {
        int c = idx >> 7, mm = idx & 127;
        sQ[mm * 36 + c] = cvt_tf32(qh[c * 1024 + m0 + mm]);
    }

    const int mg0 = m0 + w * 16 + grp;
    const int mg1 = mg0 + 8;
    const float cg00 = fmaf(((mg0 & 31) + 0.5f) * 0.0625f - 1.f, 15.5f, 31.f);
    const float cg01 = fmaf(((mg0 >> 5) + 0.5f) * 0.0625f - 1.f, 15.5f, 31.f);
    const float cg10 = fmaf(((mg1 & 31) + 0.5f) * 0.0625f - 1.f, 15.5f, 31.f);
    const float cg11 = fmaf(((mg1 >> 5) + 0.5f) * 0.0625f - 1.f, 15.5f, 31.f);

    const int rowA0 = (w * 16 + grp) * 36;
    const int rowA1 = rowA0 + 8 * 36;

    float accv[4][4];
#pragma unroll
    for (int vf = 0; vf < 4; vf++)
#pragma unroll
        for (int j = 0; j < 4; j++) accv[vf][j] = 0.f;
    float L0 = 0.f, L1 = 0.f;

    const float scale = 0.17677669529663687f;

    for (int nt = 0; nt < 16; nt++) {
        const int n0 = nt * 64;
        __syncthreads();
        for (int idx = tid; idx < 2048; idx += 256) {
            int c = idx >> 6, nn = idx & 63;
            sK[nn * 36 + c] = cvt_tf32(kh[c * 1024 + n0 + nn]);
            sV[nn * 36 + c] = cvt_tf32(vh[c * 1024 + n0 + nn]);
        }
        if (tid < 128) sPos[tid] = pos[bg * 2048 + n0 * 2 + tid];
        __syncthreads();

        // ---- QK with permuted B rows
        float sc[8][4];
#pragma unroll
        for (int nf = 0; nf < 8; nf++)
#pragma unroll
            for (int j = 0; j < 4; j++) sc[nf][j] = 0.f;

#pragma unroll
        for (int kk = 0; kk < 4; kk++) {
            const int k0 = kk * 8;
            uint32_t a0 = sQ[rowA0 + k0 + tig];
            uint32_t a1 = sQ[rowA1 + k0 + tig];
            uint32_t a2 = sQ[rowA0 + k0 + tig + 4];
            uint32_t a3 = sQ[rowA1 + k0 + tig + 4];
#pragma unroll
            for (int nf = 0; nf < 8; nf++) {
                uint32_t b0 = sK[(nf * 8 + pgrp) * 36 + k0 + tig];
                uint32_t b1 = sK[(nf * 8 + pgrp) * 36 + k0 + tig + 4];
                mma_tf32(sc[nf], a0, a1, a2, a3, b0, b1);
            }
        }

        // ---- bias + exp + PV per 8-sample slice, P stays in registers
#pragma unroll
        for (int nf = 0; nf < 8; nf++) {
            const int kb = nf * 8;
            // samples s0 = kb+tig (c0,c2), s1 = kb+tig+4 (c1,c3)
            float2 pA = *(const float2*)&sPos[2 * (kb + tig)];
            float2 pB = *(const float2*)&sPos[2 * (kb + tig + 4)];
            float pb0 = 15.5f * pA.x, pb1 = 15.5f * pA.y;
            float pb2 = 15.5f * pB.x, pb3 = 15.5f * pB.y;
            float e0 = __expf(fmaf(sc[nf][0], scale, bias_P(sR2, cg00 - pb0, cg01 - pb1)));
            float e1 = __expf(fmaf(sc[nf][1], scale, bias_P(sR2, cg00 - pb2, cg01 - pb3)));
            float e2 = __expf(fmaf(sc[nf][2], scale, bias_P(sR2, cg10 - pb0, cg11 - pb1)));
            float e3 = __expf(fmaf(sc[nf][3], scale, bias_P(sR2, cg10 - pb2, cg11 - pb3)));
            L0 += e0 + e1;
            L1 += e2 + e3;
            // A-frag: a0=P[grp][kb+tig], a1=P[grp+8][kb+tig], a2=P[grp][kb+tig+4], a3=P[grp+8][kb+tig+4]
            uint32_t a0 = cvt_tf32(e0);
            uint32_t a1 = cvt_tf32(e2);
            uint32_t a2 = cvt_tf32(e1);
            uint32_t a3 = cvt_tf32(e3);
#pragma unroll
            for (int vf = 0; vf < 4; vf++) {
                uint32_t b0 = sV[(kb + tig) * 36 + vf * 8 + grp];
                uint32_t b1 = sV[(kb + tig + 4) * 36 + vf * 8 + grp];
                mma_tf32(accv[vf], a0, a1, a2, a3, b0, b1);
            }
        }
    }

    L0 += __shfl_xor_sync(0xffffffffu, L0, 1);
    L0 += __shfl_xor_sync(0xffffffffu, L0, 2);
    L1 += __shfl_xor_sync(0xffffffffu, L1, 1);
    L1 += __shfl_xor_sync(0xffffffffu, L1, 2);
    const float rL0 = 1.f / L0;
    const float rL1 = 1.f / L1;

#pragma unroll
    for (int vf = 0; vf < 4; vf++) {
        int ch = h * 32 + vf * 8 + 2 * tig;
        int base = (b * 256 + ch) * 1024 + mg0;
        out[base]            = accv[vf][0] * rL0;
        out[base + 1024]     = accv[vf][1] * rL0;
        out[base + 8]        = accv[vf][2] * rL1;
        out[base + 1024 + 8] = accv[vf][3] * rL1;
    }
}

// ---------------- launch ----------------
extern "C" void kernel_launch(void* const* d_in, const int* in_sizes, int n_in,
                              void* d_out, int out_size)
{
    const float* x        = (const float*)d_in[0];
    const float* wq       = (const float*)d_in[1];
    const float* bq       = (const float*)d_in[2];
    const float* w_off_dw = (const float*)d_in[3];
    const float* b_off_dw = (const float*)d_in[4];
    const float* ln_g     = (const float*)d_in[5];
    const float* ln_b     = (const float*)d_in[6];
    const float* w_off_pj = (const float*)d_in[7];
    const float* wk       = (const float*)d_in[8];
    const float* bk       = (const float*)d_in[9];
    const float* wv       = (const float*)d_in[10];
    const float* bv       = (const float*)d_in[11];
    const float* wo       = (const float*)d_in[12];
    const float* bo       = (const float*)d_in[13];
    const float* rpe      = (const float*)d_in[14];
    float* out = (float*)d_out;

    float *qb, *xsb, *kb, *vb, *ob, *posb;
    cudaGetSymbolAddress((void**)&qb,   g_q);
    cudaGetSymbolAddress((void**)&xsb,  g_xs);
    cudaGetSymbolAddress((void**)&kb,   g_k);
    cudaGetSymbolAddress((void**)&vb,   g_v);
    cudaGetSymbolAddress((void**)&ob,   g_o);
    cudaGetSymbolAddress((void**)&posb, g_pos);

    const int attn_smem = 70144;
    cudaFuncSetAttribute(attn_mma, cudaFuncAttributeMaxDynamicSharedMemorySize, attn_smem);
    const int gem_smem = 55296;
    cudaFuncSetAttribute(gemm_q_tf32, cudaFuncAttributeMaxDynamicSharedMemorySize, gem_smem);
    cudaFuncSetAttribute(gemm_kv_tf32, cudaFuncAttributeMaxDynamicSharedMemorySize, gem_smem);
    const int off_smem = 163840;
    cudaFuncSetAttribute(offset_kernel, cudaFuncAttributeMaxDynamicSharedMemorySize, off_smem);

    gemm_q_tf32<<<dim3(16, 2, 4), 256, gem_smem>>>(wq, x, bq, qb);
    offset_kernel<<<64, 256, off_smem>>>(qb, w_off_dw, b_off_dw, ln_g, ln_b, w_off_pj,
                                         posb, out + 1048576, out + 1048576 + 32768);
    sample_kernel<<<64, 256>>>(x, posb, xsb);
    gemm_kv_tf32<<<dim3(16, 4, 4), 256, gem_smem>>>(wk, bk, kb, wv, bv, vb, xsb);
    attn_mma<<<dim3(8, 32), 256, attn_smem>>>(qb, kb, vb, rpe, posb, ob);
    gemm_conv<<<dim3(16, 2, 4), 256>>>(wo, ob, bo, out);
}

// round 10
// speedup vs baseline: 2.2073x; 1.1546x over previous
#include <cuda_runtime.h>
#include <math.h>
#include <stdint.h>

// B=4, C=256, H=W=32, NH=8, HC=32, G=4, GC=64, ns=1024, KK=5, ORF=2
typedef unsigned long long u64;

__device__ __forceinline__ uint32_t cvt_tf32(float x) {
    uint32_t r;
    asm("cvt.rna.tf32.f32 %0, %1;" : "=r"(r) : "f"(x));
    return r;
}
__device__ __forceinline__ void mma_tf32(float c[4],
                                         uint32_t a0, uint32_t a1, uint32_t a2, uint32_t a3,
                                         uint32_t b0, uint32_t b1) {
    asm("mma.sync.aligned.m16n8k8.row.col.f32.tf32.tf32.f32 "
        "{%0,%1,%2,%3}, {%4,%5,%6,%7}, {%8,%9}, {%0,%1,%2,%3};"
        : "+f"(c[0]), "+f"(c[1]), "+f"(c[2]), "+f"(c[3])
        : "r"(a0), "r"(a1), "r"(a2), "r"(a3), "r"(b0), "r"(b1));
}

// ---------------- scratch ----------------
__device__ float g_q [4 * 256 * 1024];
__device__ float g_xs[4 * 256 * 1024];
__device__ float g_k [4 * 256 * 1024];
__device__ float g_v [4 * 256 * 1024];
__device__ float g_o [4 * 256 * 1024];
__device__ float g_pos[16 * 1024 * 2];

// ---------------- tf32 tensor-core SGEMM, double-buffered -------------------
// 128x64 tile, 8 warps (4x2), warp 32x32, mma.m16n8k8, 1 sync per k-chunk.
// dynamic smem: 2 * (4608 + 2304) u32 = 55296 B
__device__ __forceinline__ void gemm_tf32_body(const float* __restrict__ Wm,
                                               const float* __restrict__ Xb,
                                               const float* __restrict__ bias,
                                               float* __restrict__ Yb,
                                               int m0, int n0, uint32_t* sm)
{
    uint32_t* As = sm;           // [2][128 m][32 k] stride 36
    uint32_t* Bs = sm + 9216;    // [2][64 n][32 k]  stride 36

    const int tid  = threadIdx.x;
    const int w    = tid >> 5;
    const int lane = tid & 31;
    const int grp  = lane >> 2;
    const int tig  = lane & 3;
    const int mw   = w >> 1;
    const int nw   = w & 1;

    const int a_m = tid >> 5;
    const int a_c = tid & 31;
    const int b_c = tid >> 6;
    const int b_n = tid & 63;

    float acc[2][4][4];
#pragma unroll
    for (int mf = 0; mf < 2; mf++)
#pragma unroll
        for (int nf = 0; nf < 4; nf++)
#pragma unroll
            for (int j = 0; j < 4; j++) acc[mf][nf][j] = 0.f;

    const int rowA0 = (mw * 32 + grp) * 36;
    const int rowB0 = (nw * 32 + grp) * 36;

    float wr[16], xr[8];
#pragma unroll
    for (int t = 0; t < 16; t++)
        wr[t] = Wm[(m0 + t * 8 + a_m) * 256 + a_c];
#pragma unroll
    for (int t = 0; t < 8; t++)
        xr[t] = Xb[(t * 4 + b_c) * 1024 + n0 + b_n];

    for (int kc = 0; kc < 8; kc++) {
        uint32_t* As_b = As + (kc & 1) * 4608;
        uint32_t* Bs_b = Bs + (kc & 1) * 2304;
#pragma unroll
        for (int t = 0; t < 16; t++)
            As_b[(t * 8 + a_m) * 36 + a_c] = cvt_tf32(wr[t]);
#pragma unroll
        for (int t = 0; t < 8; t++)
            Bs_b[b_n * 36 + t * 4 + b_c] = cvt_tf32(xr[t]);
        __syncthreads();

        if (kc < 7) {
            const int k0 = (kc + 1) * 32;
#pragma unroll
            for (int t = 0; t < 16; t++)
                wr[t] = Wm[(m0 + t * 8 + a_m) * 256 + k0 + a_c];
#pragma unroll
            for (int t = 0; t < 8; t++)
                xr[t] = Xb[(k0 + t * 4 + b_c) * 1024 + n0 + b_n];
        }

#pragma unroll
        for (int kk = 0; kk < 4; kk++) {
            const int kb = kk * 8 + tig;
            uint32_t a00 = As_b[rowA0 + kb];
            uint32_t a01 = As_b[rowA0 + 288 + kb];
            uint32_t a02 = As_b[rowA0 + kb + 4];
            uint32_t a03 = As_b[rowA0 + 288 + kb + 4];
            uint32_t a10 = As_b[rowA0 + 576 + kb];
            uint32_t a11 = As_b[rowA0 + 864 + kb];
            uint32_t a12 = As_b[rowA0 + 576 + kb + 4];
            uint32_t a13 = As_b[rowA0 + 864 + kb + 4];
#pragma unroll
            for (int nf = 0; nf < 4; nf++) {
                uint32_t b0 = Bs_b[rowB0 + nf * 288 + kb];
                uint32_t b1 = Bs_b[rowB0 + nf * 288 + kb + 4];
                mma_tf32(acc[0][nf], a00, a01, a02, a03, b0, b1);
                mma_tf32(acc[1][nf], a10, a11, a12, a13, b0, b1);
            }
        }
    }

    const int mr0 = m0 + mw * 32 + grp;
#pragma unroll
    for (int mf = 0; mf < 2; mf++) {
        int r0 = mr0 + mf * 16;
        float b0 = bias[r0], b1 = bias[r0 + 8];
#pragma unroll
        for (int nf = 0; nf < 4; nf++) {
            int col = n0 + nw * 32 + nf * 8 + 2 * tig;
            float2 lo = make_float2(acc[mf][nf][0] + b0, acc[mf][nf][1] + b0);
            float2 hi = make_float2(acc[mf][nf][2] + b1, acc[mf][nf][3] + b1);
            *(float2*)&Yb[r0 * 1024 + col]       = lo;
            *(float2*)&Yb[(r0 + 8) * 1024 + col] = hi;
        }
    }
}

__global__ __launch_bounds__(256, 3)
void gemm_q_tf32(const float* __restrict__ Wm, const float* __restrict__ X,
                 const float* __restrict__ bias, float* __restrict__ Y)
{
    extern __shared__ uint32_t smq[];
    gemm_tf32_body(Wm, X + blockIdx.z * 262144, bias, Y + blockIdx.z * 262144,
                   blockIdx.y * 128, blockIdx.x * 64, smq);
}

__global__ __launch_bounds__(256, 3)
void gemm_kv_tf32(const float* __restrict__ Wk, const float* __restrict__ bk,
                  float* __restrict__ Yk,
                  const float* __restrict__ Wv, const float* __restrict__ bv,
                  float* __restrict__ Yv, const float* __restrict__ X)
{
    extern __shared__ uint32_t smkv[];
    const int my = blockIdx.y;
    const float* Xb = X + blockIdx.z * 262144;
    if (my < 2)
        gemm_tf32_body(Wk, Xb, bk, Yk + blockIdx.z * 262144, my * 128, blockIdx.x * 64, smkv);
    else
        gemm_tf32_body(Wv, Xb, bv, Yv + blockIdx.z * 262144, (my - 2) * 128, blockIdx.x * 64, smkv);
}

// ---------------- offset pipeline: smem-staged conv, activations cached -----
__global__ __launch_bounds__(256)
void offset_kernel(const float* __restrict__ q, const float* __restrict__ w_dw,
                   const float* __restrict__ b_dw, const float* __restrict__ ln_g,
                   const float* __restrict__ ln_b, const float* __restrict__ wpj,
                   float* __restrict__ pos_buf, float* __restrict__ out_pos,
                   float* __restrict__ out_ref)
{
    extern __shared__ float dsm[];
    float* simg = dsm;               // [c][384]
    float* sa   = dsm + 64 * 384;    // [c][256]

    __shared__ float sw[1600];
    __shared__ float sb[64], sg[64], sbt[64], spj0[64], spj1[64];

    const int tid = threadIdx.x;
    for (int t = tid; t < 1600; t += 256) sw[t] = w_dw[t];
    if (tid < 64) {
        sb[tid] = b_dw[tid]; sg[tid] = ln_g[tid]; sbt[tid] = ln_b[tid];
        spj0[tid] = wpj[tid]; spj1[tid] = wpj[64 + tid];
    }

    const int bi = blockIdx.x;
    const int bg = bi >> 2;
    const int i0 = (bi & 3) * 8;
    const float* qb = q + bg * 65536;

    for (int t = tid; t < 24576; t += 256) {
        int c  = t / 384;
        int r2 = t - c * 384;
        int yy = i0 - 2 + (r2 >> 5);
        int col = r2 & 31;
        float vv = 0.f;
        if ((unsigned)yy < 32u) vv = qb[c * 1024 + yy * 32 + col];
        simg[c * 384 + r2] = vv;
    }
    __syncthreads();

    const int li = tid >> 5;
    const int j  = tid & 31;
    const int i  = i0 + li;

    float s1 = 0.f, s2 = 0.f;
    for (int c = 0; c < 64; c++) {
        const float* ic = simg + c * 384 + li * 32;
        const float* wc = sw + c * 25;
        float a = sb[c];
#pragma unroll
        for (int dy = 0; dy < 5; dy++) {
            const float* irow = ic + dy * 32;
#pragma unroll
            for (int dx = 0; dx < 5; dx++) {
                int xx = j + dx - 2;
                float vv = ((unsigned)xx < 32u) ? irow[xx] : 0.f;
                a = fmaf(vv, wc[dy * 5 + dx], a);
            }
        }
        s1 += a;
        s2 = fmaf(a, a, s2);
        sa[c * 256 + tid] = a;
    }
    float mu   = s1 * 0.015625f;
    float var  = s2 * 0.015625f - mu * mu;
    float rstd = rsqrtf(var + 1e-5f);

    float o0 = 0.f, o1 = 0.f;
    for (int c = 0; c < 64; c++) {
        float a  = sa[c * 256 + tid];
        float t2 = fmaf((a - mu) * rstd, sg[c], sbt[c]);
        float gl = 0.5f * t2 * (1.f + erff(t2 * 0.70710678118654752f));
        o0 = fmaf(gl, spj0[c], o0);
        o1 = fmaf(gl, spj1[c], o1);
    }
    float off0 = tanhf(o0) * 0.0625f;
    float off1 = tanhf(o1) * 0.0625f;
    float r0 = (j + 0.5f) * 0.0625f - 1.f;
    float r1 = (i + 0.5f) * 0.0625f - 1.f;
    float P0 = off0 + r0, P1 = off1 + r1;

    const int pix = bi * 256 + tid;
    pos_buf[pix * 2]     = P0;
    pos_buf[pix * 2 + 1] = P1;
    out_pos[pix * 2]     = P0;
    out_pos[pix * 2 + 1] = P1;
    out_ref[pix * 2]     = r0;
    out_ref[pix * 2 + 1] = r1;
}

// ---------------- bilinear sample of x at pos -> xs --------------------------
// 512 blocks x 256 threads: block = 32 points x 64 channels; warp w = 8-channel
// slice, lane = point. Fully coalesced STG. 512*32 = 16384 points total.
__global__ __launch_bounds__(256)
void sample_kernel(const float* __restrict__ x, const float* __restrict__ pos_buf,
                   float* __restrict__ xs)
{
    const int w    = threadIdx.x >> 5;
    const int lane = threadIdx.x & 31;
    const int idx  = blockIdx.x * 32 + lane;   // bg*1024 + n, 0..16383
    const float P0 = pos_buf[idx * 2];
    const float P1 = pos_buf[idx * 2 + 1];
    const float gxp = (P1 + 1.f) * 15.5f;
    const float gyp = (P0 + 1.f) * 15.5f;
    float x0f = floorf(gxp), y0f = floorf(gyp);
    float x1f = x0f + 1.f,  y1f = y0f + 1.f;
    float wx1 = gxp - x0f, wx0 = 1.f - wx1;
    float wy1 = gyp - y0f, wy0 = 1.f - wy1;
    bool vx0 = (x0f >= 0.f) && (x0f <= 31.f);
    bool vx1 = (x1f >= 0.f) && (x1f <= 31.f);
    bool vy0 = (y0f >= 0.f) && (y0f <= 31.f);
    bool vy1 = (y1f >= 0.f) && (y1f <= 31.f);
    int X0 = (int)fminf(fmaxf(x0f, 0.f), 31.f);
    int X1 = (int)fminf(fmaxf(x1f, 0.f), 31.f);
    int Y0 = (int)fminf(fmaxf(y0f, 0.f), 31.f);
    int Y1 = (int)fminf(fmaxf(y1f, 0.f), 31.f);
    float w00 = (vy0 && vx0) ? wy0 * wx0 : 0.f;
    float w01 = (vy0 && vx1) ? wy0 * wx1 : 0.f;
    float w10 = (vy1 && vx0) ? wy1 * wx0 : 0.f;
    float w11 = (vy1 && vx1) ? wy1 * wx1 : 0.f;
    int i00 = Y0 * 32 + X0, i01 = Y0 * 32 + X1;
    int i10 = Y1 * 32 + X0, i11 = Y1 * 32 + X1;

    const int bg = idx >> 10, n = idx & 1023;
    const float* xb = x + bg * 65536 + w * 8 * 1024;
    float* xo = xs + bg * 65536 + w * 8 * 1024 + n;
#pragma unroll
    for (int c = 0; c < 8; c++) {
        const float* xc = xb + c * 1024;
        float vout = w00 * xc[i00] + w01 * xc[i01] + w10 * xc[i10] + w11 * xc[i11];
        xo[c * 1024] = vout;
    }
}

// ---------------- RPE bilinear from PAIRED table, F2I floor (no MUFU FRND) --
__device__ __forceinline__ float bias_P(const float2* __restrict__ sR2,
                                        float gyp, float gxp)
{
    int yi = __float2int_rd(gyp);
    int xi = __float2int_rd(gxp);
    float wy1 = gyp - __int2float_rn(yi);
    float wx1 = gxp - __int2float_rn(xi);
    float2 p0 = sR2[(xi << 6) + yi];
    float2 p1 = sR2[(xi << 6) + 64 + yi];
    float v0 = fmaf(wy1, p0.y - p0.x, p0.x);
    float v1 = fmaf(wy1, p1.y - p1.x, p1.x);
    return fmaf(wx1, v1 - v0, v0);
}

// ---------------- fused attention on tensor cores, register-resident P -------
__global__ __launch_bounds__(256, 3)
void attn_mma(const float* __restrict__ q, const float* __restrict__ k,
              const float* __restrict__ v, const float* __restrict__ rpe,
              const float* __restrict__ pos, float* __restrict__ out)
{
    extern __shared__ float smf[];
    uint32_t* sQ  = (uint32_t*)smf;          // [m=128][c=32] stride 36 : 4608
    uint32_t* sK  = sQ + 4608;               // [n=64][c=32]  stride 36 : 2304
    uint32_t* sV  = sK + 2304;               // [s=64][ch=32] stride 36 : 2304
    float*  sPos  = (float*)(sV + 2304);     // 128
    float2* sR2   = (float2*)(sPos + 128);   // 4096 float2

    const int bh = blockIdx.y;
    const int b  = bh >> 3, h = bh & 7;
    const int gq = h >> 1;
    const int bg = b * 4 + gq;
    const int m0 = blockIdx.x * 128;
    const float* rpe_h = rpe + h * 3969;

    const int tid  = threadIdx.x;
    const int w    = tid >> 5;
    const int lane = tid & 31;
    const int grp  = lane >> 2;
    const int tig  = lane & 3;
    const int pgrp = (grp & 1) ? (grp >> 1) + 4 : (grp >> 1);

    for (int t = tid; t < 4096; t += 256) sR2[t] = make_float2(0.f, 0.f);
    __syncthreads();
    for (int t = tid; t < 3969; t += 256) {
        int r = t / 63, c2 = t - r * 63;
        float val = rpe_h[t];
        sR2[(c2 << 6) + r].x = val;
        if (r > 0) sR2[(c2 << 6) + r - 1].y = val;
    }

    const float* qh = q + (b * 256 + h * 32) * 1024;
    const float* kh = k + (b * 256 + h * 32) * 1024;
    const float* vh = v + (b * 256 + h * 32) * 1024;

    for (int idx = tid; idx < 4096; idx += 256) {
        int c = idx >> 7, mm = idx & 127;
        sQ[mm * 36 + c] = cvt_tf32(qh[c * 1024 + m0 + mm]);
    }

    const int mg0 = m0 + w * 16 + grp;
    const int mg1 = mg0 + 8;
    const float cg00 = fmaf(((mg0 & 31) + 0.5f) * 0.0625f - 1.f, 15.5f, 31.f);
    const float cg01 = fmaf(((mg0 >> 5) + 0.5f) * 0.0625f - 1.f, 15.5f, 31.f);
    const float cg10 = fmaf(((mg1 & 31) + 0.5f) * 0.0625f - 1.f, 15.5f, 31.f);
    const float cg11 = fmaf(((mg1 >> 5) + 0.5f) * 0.0625f - 1.f, 15.5f, 31.f);

    const int rowA0 = (w * 16 + grp) * 36;
    const int rowA1 = rowA0 + 8 * 36;

    float accv[4][4];
#pragma unroll
    for (int vf = 0; vf < 4; vf++)
#pragma unroll
        for (int j = 0; j < 4; j++) accv[vf][j] = 0.f;
    float L0 = 0.f, L1 = 0.f;

    const float scale = 0.17677669529663687f;

    for (int nt = 0; nt < 16; nt++) {
        const int n0 = nt * 64;
        __syncthreads();
        for (int idx = tid; idx < 2048; idx += 256) {
            int c = idx >> 6, nn = idx & 63;
            sK[nn * 36 + c] = cvt_tf32(kh[c * 1024 + n0 + nn]);
            sV[nn * 36 + c] = cvt_tf32(vh[c * 1024 + n0 + nn]);
        }
        if (tid < 128) sPos[tid] = pos[bg * 2048 + n0 * 2 + tid];
        __syncthreads();

        // ---- QK with permuted B rows
        float sc[8][4];
#pragma unroll
        for (int nf = 0; nf < 8; nf++)
#pragma unroll
            for (int j = 0; j < 4; j++) sc[nf][j] = 0.f;

#pragma unroll
        for (int kk = 0; kk < 4; kk++) {
            const int k0 = kk * 8;
            uint32_t a0 = sQ[rowA0 + k0 + tig];
            uint32_t a1 = sQ[rowA1 + k0 + tig];
            uint32_t a2 = sQ[rowA0 + k0 + tig + 4];
            uint32_t a3 = sQ[rowA1 + k0 + tig + 4];
#pragma unroll
            for (int nf = 0; nf < 8; nf++) {
                uint32_t b0 = sK[(nf * 8 + pgrp) * 36 + k0 + tig];
                uint32_t b1 = sK[(nf * 8 + pgrp) * 36 + k0 + tig + 4];
                mma_tf32(sc[nf], a0, a1, a2, a3, b0, b1);
            }
        }

        // ---- bias + exp + PV per 8-sample slice, P stays in registers
#pragma unroll
        for (int nf = 0; nf < 8; nf++) {
            const int kb = nf * 8;
            float2 pA = *(const float2*)&sPos[2 * (kb + tig)];
            float2 pB = *(const float2*)&sPos[2 * (kb + tig + 4)];
            float pb0 = 15.5f * pA.x, pb1 = 15.5f * pA.y;
            float pb2 = 15.5f * pB.x, pb3 = 15.5f * pB.y;
            float e0 = __expf(fmaf(sc[nf][0], scale, bias_P(sR2, cg00 - pb0, cg01 - pb1)));
            float e1 = __expf(fmaf(sc[nf][1], scale, bias_P(sR2, cg00 - pb2, cg01 - pb3)));
            float e2 = __expf(fmaf(sc[nf][2], scale, bias_P(sR2, cg10 - pb0, cg11 - pb1)));
            float e3 = __expf(fmaf(sc[nf][3], scale, bias_P(sR2, cg10 - pb2, cg11 - pb3)));
            L0 += e0 + e1;
            L1 += e2 + e3;
            uint32_t a0 = cvt_tf32(e0);
            uint32_t a1 = cvt_tf32(e2);
            uint32_t a2 = cvt_tf32(e1);
            uint32_t a3 = cvt_tf32(e3);
#pragma unroll
            for (int vf = 0; vf < 4; vf++) {
                uint32_t b0 = sV[(kb + tig) * 36 + vf * 8 + grp];
                uint32_t b1 = sV[(kb + tig + 4) * 36 + vf * 8 + grp];
                mma_tf32(accv[vf], a0, a1, a2, a3, b0, b1);
            }
        }
    }

    L0 += __shfl_xor_sync(0xffffffffu, L0, 1);
    L0 += __shfl_xor_sync(0xffffffffu, L0, 2);
    L1 += __shfl_xor_sync(0xffffffffu, L1, 1);
    L1 += __shfl_xor_sync(0xffffffffu, L1, 2);
    const float rL0 = 1.f / L0;
    const float rL1 = 1.f / L1;

#pragma unroll
    for (int vf = 0; vf < 4; vf++) {
        int ch = h * 32 + vf * 8 + 2 * tig;
        int base = (b * 256 + ch) * 1024 + mg0;
        out[base]            = accv[vf][0] * rL0;
        out[base + 1024]     = accv[vf][1] * rL0;
        out[base + 8]        = accv[vf][2] * rL1;
        out[base + 1024 + 8] = accv[vf][3] * rL1;
    }
}

// ---------------- launch ----------------
extern "C" void kernel_launch(void* const* d_in, const int* in_sizes, int n_in,
                              void* d_out, int out_size)
{
    const float* x        = (const float*)d_in[0];
    const float* wq       = (const float*)d_in[1];
    const float* bq       = (const float*)d_in[2];
    const float* w_off_dw = (const float*)d_in[3];
    const float* b_off_dw = (const float*)d_in[4];
    const float* ln_g     = (const float*)d_in[5];
    const float* ln_b     = (const float*)d_in[6];
    const float* w_off_pj = (const float*)d_in[7];
    const float* wk       = (const float*)d_in[8];
    const float* bk       = (const float*)d_in[9];
    const float* wv       = (const float*)d_in[10];
    const float* bv       = (const float*)d_in[11];
    const float* wo       = (const float*)d_in[12];
    const float* bo       = (const float*)d_in[13];
    const float* rpe      = (const float*)d_in[14];
    float* out = (float*)d_out;

    float *qb, *xsb, *kb, *vb, *ob, *posb;
    cudaGetSymbolAddress((void**)&qb,   g_q);
    cudaGetSymbolAddress((void**)&xsb,  g_xs);
    cudaGetSymbolAddress((void**)&kb,   g_k);
    cudaGetSymbolAddress((void**)&vb,   g_v);
    cudaGetSymbolAddress((void**)&ob,   g_o);
    cudaGetSymbolAddress((void**)&posb, g_pos);

    const int attn_smem = 70144;
    cudaFuncSetAttribute(attn_mma, cudaFuncAttributeMaxDynamicSharedMemorySize, attn_smem);
    const int gem_smem = 55296;
    cudaFuncSetAttribute(gemm_q_tf32, cudaFuncAttributeMaxDynamicSharedMemorySize, gem_smem);
    cudaFuncSetAttribute(gemm_kv_tf32, cudaFuncAttributeMaxDynamicSharedMemorySize, gem_smem);
    const int off_smem = 163840;
    cudaFuncSetAttribute(offset_kernel, cudaFuncAttributeMaxDynamicSharedMemorySize, off_smem);

    gemm_q_tf32<<<dim3(16, 2, 4), 256, gem_smem>>>(wq, x, bq, qb);
    offset_kernel<<<64, 256, off_smem>>>(qb, w_off_dw, b_off_dw, ln_g, ln_b, w_off_pj,
                                         posb, out + 1048576, out + 1048576 + 32768);
    sample_kernel<<<512, 256>>>(x, posb, xsb);
    gemm_kv_tf32<<<dim3(16, 4, 4), 256, gem_smem>>>(wk, bk, kb, wv, bv, vb, xsb);
    attn_mma<<<dim3(8, 32), 256, attn_smem>>>(qb, kb, vb, rpe, posb, ob);
    gemm_q_tf32<<<dim3(16, 2, 4), 256, gem_smem>>>(wo, ob, bo, out);
}

// round 11
// speedup vs baseline: 2.2599x; 1.0238x over previous
#include <cuda_runtime.h>
#include <cuda_bf16.h>
#include <math.h>
#include <stdint.h>

// B=4, C=256, H=W=32, NH=8, HC=32, G=4, GC=64, ns=1024, KK=5, ORF=2
typedef unsigned long long u64;

__device__ __forceinline__ uint32_t cvt_tf32(float x) {
    uint32_t r;
    asm("cvt.rna.tf32.f32 %0, %1;" : "=r"(r) : "f"(x));
    return r;
}
__device__ __forceinline__ void mma_tf32(float c[4],
                                         uint32_t a0, uint32_t a1, uint32_t a2, uint32_t a3,
                                         uint32_t b0, uint32_t b1) {
    asm("mma.sync.aligned.m16n8k8.row.col.f32.tf32.tf32.f32 "
        "{%0,%1,%2,%3}, {%4,%5,%6,%7}, {%8,%9}, {%0,%1,%2,%3};"
        : "+f"(c[0]), "+f"(c[1]), "+f"(c[2]), "+f"(c[3])
        : "r"(a0), "r"(a1), "r"(a2), "r"(a3), "r"(b0), "r"(b1));
}

// ---------------- scratch ----------------
__device__ float g_q [4 * 256 * 1024];
__device__ float g_xs[4 * 256 * 1024];
__device__ float g_k [4 * 256 * 1024];
__device__ float g_v [4 * 256 * 1024];
__device__ float g_o [4 * 256 * 1024];
__device__ float g_pos[16 * 1024 * 2];

// ---------------- tf32 tensor-core SGEMM, double-buffered -------------------
__device__ __forceinline__ void gemm_tf32_body(const float* __restrict__ Wm,
                                               const float* __restrict__ Xb,
                                               const float* __restrict__ bias,
                                               float* __restrict__ Yb,
                                               int m0, int n0, uint32_t* sm)
{
    uint32_t* As = sm;           // [2][128 m][32 k] stride 36
    uint32_t* Bs = sm + 9216;    // [2][64 n][32 k]  stride 36

    const int tid  = threadIdx.x;
    const int w    = tid >> 5;
    const int lane = tid & 31;
    const int grp  = lane >> 2;
    const int tig  = lane & 3;
    const int mw   = w >> 1;
    const int nw   = w & 1;

    const int a_m = tid >> 5;
    const int a_c = tid & 31;
    const int b_c = tid >> 6;
    const int b_n = tid & 63;

    float acc[2][4][4];
#pragma unroll
    for (int mf = 0; mf < 2; mf++)
#pragma unroll
        for (int nf = 0; nf < 4; nf++)
#pragma unroll
            for (int j = 0; j < 4; j++) acc[mf][nf][j] = 0.f;

    const int rowA0 = (mw * 32 + grp) * 36;
    const int rowB0 = (nw * 32 + grp) * 36;

    float wr[16], xr[8];
#pragma unroll
    for (int t = 0; t < 16; t++)
        wr[t] = Wm[(m0 + t * 8 + a_m) * 256 + a_c];
#pragma unroll
    for (int t = 0; t < 8; t++)
        xr[t] = Xb[(t * 4 + b_c) * 1024 + n0 + b_n];

    for (int kc = 0; kc < 8; kc++) {
        uint32_t* As_b = As + (kc & 1) * 4608;
        uint32_t* Bs_b = Bs + (kc & 1) * 2304;
#pragma unroll
        for (int t = 0; t < 16; t++)
            As_b[(t * 8 + a_m) * 36 + a_c] = cvt_tf32(wr[t]);
#pragma unroll
        for (int t = 0; t < 8; t++)
            Bs_b[b_n * 36 + t * 4 + b_c] = cvt_tf32(xr[t]);
        __syncthreads();

        if (kc < 7) {
            const int k0 = (kc + 1) * 32;
#pragma unroll
            for (int t = 0; t < 16; t++)
                wr[t] = Wm[(m0 + t * 8 + a_m) * 256 + k0 + a_c];
#pragma unroll
            for (int t = 0; t < 8; t++)
                xr[t] = Xb[(k0 + t * 4 + b_c) * 1024 + n0 + b_n];
        }

#pragma unroll
        for (int kk = 0; kk < 4; kk++) {
            const int kb = kk * 8 + tig;
            uint32_t a00 = As_b[rowA0 + kb];
            uint32_t a01 = As_b[rowA0 + 288 + kb];
            uint32_t a02 = As_b[rowA0 + kb + 4];
            uint32_t a03 = As_b[rowA0 + 288 + kb + 4];
            uint32_t a10 = As_b[rowA0 + 576 + kb];
            uint32_t a11 = As_b[rowA0 + 864 + kb];
            uint32_t a12 = As_b[rowA0 + 576 + kb + 4];
            uint32_t a13 = As_b[rowA0 + 864 + kb + 4];
#pragma unroll
            for (int nf = 0; nf < 4; nf++) {
                uint32_t b0 = Bs_b[rowB0 + nf * 288 + kb];
                uint32_t b1 = Bs_b[rowB0 + nf * 288 + kb + 4];
                mma_tf32(acc[0][nf], a00, a01, a02, a03, b0, b1);
                mma_tf32(acc[1][nf], a10, a11, a12, a13, b0, b1);
            }
        }
    }

    const int mr0 = m0 + mw * 32 + grp;
#pragma unroll
    for (int mf = 0; mf < 2; mf++) {
        int r0 = mr0 + mf * 16;
        float b0 = bias[r0], b1 = bias[r0 + 8];
#pragma unroll
        for (int nf = 0; nf < 4; nf++) {
            int col = n0 + nw * 32 + nf * 8 + 2 * tig;
            float2 lo = make_float2(acc[mf][nf][0] + b0, acc[mf][nf][1] + b0);
            float2 hi = make_float2(acc[mf][nf][2] + b1, acc[mf][nf][3] + b1);
            *(float2*)&Yb[r0 * 1024 + col]       = lo;
            *(float2*)&Yb[(r0 + 8) * 1024 + col] = hi;
        }
    }
}

__global__ __launch_bounds__(256, 3)
void gemm_q_tf32(const float* __restrict__ Wm, const float* __restrict__ X,
                 const float* __restrict__ bias, float* __restrict__ Y)
{
    extern __shared__ uint32_t smq[];
    gemm_tf32_body(Wm, X + blockIdx.z * 262144, bias, Y + blockIdx.z * 262144,
                   blockIdx.y * 128, blockIdx.x * 64, smq);
}

__global__ __launch_bounds__(256, 3)
void gemm_kv_tf32(const float* __restrict__ Wk, const float* __restrict__ bk,
                  float* __restrict__ Yk,
                  const float* __restrict__ Wv, const float* __restrict__ bv,
                  float* __restrict__ Yv, const float* __restrict__ X)
{
    extern __shared__ uint32_t smkv[];
    const int my = blockIdx.y;
    const float* Xb = X + blockIdx.z * 262144;
    if (my < 2)
        gemm_tf32_body(Wk, Xb, bk, Yk + blockIdx.z * 262144, my * 128, blockIdx.x * 64, smkv);
    else
        gemm_tf32_body(Wv, Xb, bv, Yv + blockIdx.z * 262144, (my - 2) * 128, blockIdx.x * 64, smkv);
}

// ---------------- offset pipeline: smem-staged conv, activations cached -----
__global__ __launch_bounds__(256)
void offset_kernel(const float* __restrict__ q, const float* __restrict__ w_dw,
                   const float* __restrict__ b_dw, const float* __restrict__ ln_g,
                   const float* __restrict__ ln_b, const float* __restrict__ wpj,
                   float* __restrict__ pos_buf, float* __restrict__ out_pos,
                   float* __restrict__ out_ref)
{
    extern __shared__ float dsm[];
    float* simg = dsm;               // [c][384]
    float* sa   = dsm + 64 * 384;    // [c][256]

    __shared__ float sw[1600];
    __shared__ float sb[64], sg[64], sbt[64], spj0[64], spj1[64];

    const int tid = threadIdx.x;
    for (int t = tid; t < 1600; t += 256) sw[t] = w_dw[t];
    if (tid < 64) {
        sb[tid] = b_dw[tid]; sg[tid] = ln_g[tid]; sbt[tid] = ln_b[tid];
        spj0[tid] = wpj[tid]; spj1[tid] = wpj[64 + tid];
    }

    const int bi = blockIdx.x;
    const int bg = bi >> 2;
    const int i0 = (bi & 3) * 8;
    const float* qb = q + bg * 65536;

    for (int t = tid; t < 24576; t += 256) {
        int c  = t / 384;
        int r2 = t - c * 384;
        int yy = i0 - 2 + (r2 >> 5);
        int col = r2 & 31;
        float vv = 0.f;
        if ((unsigned)yy < 32u) vv = qb[c * 1024 + yy * 32 + col];
        simg[c * 384 + r2] = vv;
    }
    __syncthreads();

    const int li = tid >> 5;
    const int j  = tid & 31;
    const int i  = i0 + li;

    float s1 = 0.f, s2 = 0.f;
    for (int c = 0; c < 64; c++) {
        const float* ic = simg + c * 384 + li * 32;
        const float* wc = sw + c * 25;
        float a = sb[c];
#pragma unroll
        for (int dy = 0; dy < 5; dy++) {
            const float* irow = ic + dy * 32;
#pragma unroll
            for (int dx = 0; dx < 5; dx++) {
                int xx = j + dx - 2;
                float vv = ((unsigned)xx < 32u) ? irow[xx] : 0.f;
                a = fmaf(vv, wc[dy * 5 + dx], a);
            }
        }
        s1 += a;
        s2 = fmaf(a, a, s2);
        sa[c * 256 + tid] = a;
    }
    float mu   = s1 * 0.015625f;
    float var  = s2 * 0.015625f - mu * mu;
    float rstd = rsqrtf(var + 1e-5f);

    float o0 = 0.f, o1 = 0.f;
    for (int c = 0; c < 64; c++) {
        float a  = sa[c * 256 + tid];
        float t2 = fmaf((a - mu) * rstd, sg[c], sbt[c]);
        float gl = 0.5f * t2 * (1.f + erff(t2 * 0.70710678118654752f));
        o0 = fmaf(gl, spj0[c], o0);
        o1 = fmaf(gl, spj1[c], o1);
    }
    float off0 = tanhf(o0) * 0.0625f;
    float off1 = tanhf(o1) * 0.0625f;
    float r0 = (j + 0.5f) * 0.0625f - 1.f;
    float r1 = (i + 0.5f) * 0.0625f - 1.f;
    float P0 = off0 + r0, P1 = off1 + r1;

    const int pix = bi * 256 + tid;
    pos_buf[pix * 2]     = P0;
    pos_buf[pix * 2 + 1] = P1;
    out_pos[pix * 2]     = P0;
    out_pos[pix * 2 + 1] = P1;
    out_ref[pix * 2]     = r0;
    out_ref[pix * 2 + 1] = r1;
}

// ---------------- bilinear sample of x at pos -> xs --------------------------
// 512 blocks x 256 threads: block = 32 points x 64 channels; warp = 8-ch slice.
__global__ __launch_bounds__(256)
void sample_kernel(const float* __restrict__ x, const float* __restrict__ pos_buf,
                   float* __restrict__ xs)
{
    const int w    = threadIdx.x >> 5;
    const int lane = threadIdx.x & 31;
    const int idx  = blockIdx.x * 32 + lane;   // 0..16383
    const float P0 = pos_buf[idx * 2];
    const float P1 = pos_buf[idx * 2 + 1];
    const float gxp = (P1 + 1.f) * 15.5f;
    const float gyp = (P0 + 1.f) * 15.5f;
    float x0f = floorf(gxp), y0f = floorf(gyp);
    float x1f = x0f + 1.f,  y1f = y0f + 1.f;
    float wx1 = gxp - x0f, wx0 = 1.f - wx1;
    float wy1 = gyp - y0f, wy0 = 1.f - wy1;
    bool vx0 = (x0f >= 0.f) && (x0f <= 31.f);
    bool vx1 = (x1f >= 0.f) && (x1f <= 31.f);
    bool vy0 = (y0f >= 0.f) && (y0f <= 31.f);
    bool vy1 = (y1f >= 0.f) && (y1f <= 31.f);
    int X0 = (int)fminf(fmaxf(x0f, 0.f), 31.f);
    int X1 = (int)fminf(fmaxf(x1f, 0.f), 31.f);
    int Y0 = (int)fminf(fmaxf(y0f, 0.f), 31.f);
    int Y1 = (int)fminf(fmaxf(y1f, 0.f), 31.f);
    float w00 = (vy0 && vx0) ? wy0 * wx0 : 0.f;
    float w01 = (vy0 && vx1) ? wy0 * wx1 : 0.f;
    float w10 = (vy1 && vx0) ? wy1 * wx0 : 0.f;
    float w11 = (vy1 && vx1) ? wy1 * wx1 : 0.f;
    int i00 = Y0 * 32 + X0, i01 = Y0 * 32 + X1;
    int i10 = Y1 * 32 + X0, i11 = Y1 * 32 + X1;

    const int bg = idx >> 10, n = idx & 1023;
    const float* xb = x + bg * 65536 + w * 8 * 1024;
    float* xo = xs + bg * 65536 + w * 8 * 1024 + n;
#pragma unroll
    for (int c = 0; c < 8; c++) {
        const float* xc = xb + c * 1024;
        float vout = w00 * xc[i00] + w01 * xc[i01] + w10 * xc[i10] + w11 * xc[i11];
        xo[c * 1024] = vout;
    }
}

// ---------------- RPE bilinear from bf16x2 PAIRED table ----------------------
// entry[x*64+y] = (bf16(T[y][x]), bf16(T[y+1][x])); bf16->f32 = bit shift.
__device__ __forceinline__ float bias_Pb(const uint32_t* __restrict__ sR,
                                         float gyp, float gxp)
{
    int yi = __float2int_rd(gyp);
    int xi = __float2int_rd(gxp);
    float wy1 = gyp - __int2float_rn(yi);
    float wx1 = gxp - __int2float_rn(xi);
    uint32_t w0 = sR[(xi << 6) + yi];
    uint32_t w1 = sR[(xi << 6) + 64 + yi];
    float p0x = __uint_as_float(w0 << 16);
    float p0y = __uint_as_float(w0 & 0xFFFF0000u);
    float p1x = __uint_as_float(w1 << 16);
    float p1y = __uint_as_float(w1 & 0xFFFF0000u);
    float v0 = fmaf(wy1, p0y - p0x, p0x);
    float v1 = fmaf(wy1, p1y - p1x, p1x);
    return fmaf(wx1, v1 - v0, v0);
}

// ---------------- fused attention: tensor cores, reg-resident P,
//                  double-buffered K/V/pos staging (1 sync per tile) ----------
// smem words: sQ 4608 | sK 2x2304 | sV 2x2304 | sPos 2x128 | sRpe(bf16x2) 4096
//           = 18176 words = 72704 B ; occ 3.
__global__ __launch_bounds__(256, 3)
void attn_mma(const float* __restrict__ q, const float* __restrict__ k,
              const float* __restrict__ v, const float* __restrict__ rpe,
              const float* __restrict__ pos, float* __restrict__ out)
{
    extern __shared__ float smf[];
    uint32_t* sQ   = (uint32_t*)smf;           // 4608
    uint32_t* sK   = sQ + 4608;                // 2 x 2304
    uint32_t* sV   = sK + 4608;                // 2 x 2304
    float*    sPos = (float*)(sV + 4608);      // 2 x 128
    uint32_t* sRb  = (uint32_t*)(sPos + 256);  // 4096 (bf16x2 pairs)

    const int bh = blockIdx.y;
    const int b  = bh >> 3, h = bh & 7;
    const int gq = h >> 1;
    const int bg = b * 4 + gq;
    const int m0 = blockIdx.x * 128;
    const float* rpe_h = rpe + h * 3969;

    const int tid  = threadIdx.x;
    const int w    = tid >> 5;
    const int lane = tid & 31;
    const int grp  = lane >> 2;
    const int tig  = lane & 3;
    const int pgrp = (grp & 1) ? (grp >> 1) + 4 : (grp >> 1);

    // bf16x2 paired RPE table, zero pad
    for (int t = tid; t < 4096; t += 256) sRb[t] = 0u;
    __syncthreads();
    {
        __nv_bfloat16* sRh = (__nv_bfloat16*)sRb;
        for (int t = tid; t < 3969; t += 256) {
            int r = t / 63, c2 = t - r * 63;
            __nv_bfloat16 bv = __float2bfloat16(rpe_h[t]);
            sRh[(((c2 << 6) + r) << 1)] = bv;                 // .x of (y=r)
            if (r > 0) sRh[(((c2 << 6) + r - 1) << 1) + 1] = bv;  // .y of (y=r-1)
        }
    }

    const float* qh = q + (b * 256 + h * 32) * 1024;
    const float* kh = k + (b * 256 + h * 32) * 1024;
    const float* vh = v + (b * 256 + h * 32) * 1024;

    for (int idx = tid; idx < 4096; idx += 256) {
        int c = idx >> 7, mm = idx & 127;
        sQ[mm * 36 + c] = cvt_tf32(qh[c * 1024 + m0 + mm]);
    }

    const int mg0 = m0 + w * 16 + grp;
    const int mg1 = mg0 + 8;
    const float cg00 = fmaf(((mg0 & 31) + 0.5f) * 0.0625f - 1.f, 15.5f, 31.f);
    const float cg01 = fmaf(((mg0 >> 5) + 0.5f) * 0.0625f - 1.f, 15.5f, 31.f);
    const float cg10 = fmaf(((mg1 & 31) + 0.5f) * 0.0625f - 1.f, 15.5f, 31.f);
    const float cg11 = fmaf(((mg1 >> 5) + 0.5f) * 0.0625f - 1.f, 15.5f, 31.f);

    const int rowA0 = (w * 16 + grp) * 36;
    const int rowA1 = rowA0 + 8 * 36;

    float accv[4][4];
#pragma unroll
    for (int vf = 0; vf < 4; vf++)
#pragma unroll
        for (int j = 0; j < 4; j++) accv[vf][j] = 0.f;
    float L0 = 0.f, L1 = 0.f;

    const float scale = 0.17677669529663687f;

    // ---- prefetch tile 0 K/V/pos into registers
    const int st_c = tid >> 6;    // 0..3
    const int st_n = tid & 63;
    float kf[8], vfr[8], posr;
#pragma unroll
    for (int t = 0; t < 8; t++) {
        kf[t]  = kh[(t * 4 + st_c) * 1024 + st_n];
        vfr[t] = vh[(t * 4 + st_c) * 1024 + st_n];
    }
    posr = (tid < 128) ? pos[bg * 2048 + tid] : 0.f;

    for (int nt = 0; nt < 16; nt++) {
        uint32_t* sKb = sK + (nt & 1) * 2304;
        uint32_t* sVb = sV + (nt & 1) * 2304;
        float*    sPb = sPos + (nt & 1) * 128;
#pragma unroll
        for (int t = 0; t < 8; t++) {
            sKb[st_n * 36 + t * 4 + st_c] = cvt_tf32(kf[t]);
            sVb[st_n * 36 + t * 4 + st_c] = cvt_tf32(vfr[t]);
        }
        if (tid < 128) sPb[tid] = posr;
        __syncthreads();

        if (nt < 15) {
            const int n0n = (nt + 1) * 64;
#pragma unroll
            for (int t = 0; t < 8; t++) {
                kf[t]  = kh[(t * 4 + st_c) * 1024 + n0n + st_n];
                vfr[t] = vh[(t * 4 + st_c) * 1024 + n0n + st_n];
            }
            posr = (tid < 128) ? pos[bg * 2048 + n0n * 2 + tid] : 0.f;
        }

        // ---- QK with permuted B rows
        float sc[8][4];
#pragma unroll
        for (int nf = 0; nf < 8; nf++)
#pragma unroll
            for (int j = 0; j < 4; j++) sc[nf][j] = 0.f;

#pragma unroll
        for (int kk = 0; kk < 4; kk++) {
            const int k0 = kk * 8;
            uint32_t a0 = sQ[rowA0 + k0 + tig];
            uint32_t a1 = sQ[rowA1 + k0 + tig];
            uint32_t a2 = sQ[rowA0 + k0 + tig + 4];
            uint32_t a3 = sQ[rowA1 + k0 + tig + 4];
#pragma unroll
            for (int nf = 0; nf < 8; nf++) {
                uint32_t b0 = sKb[(nf * 8 + pgrp) * 36 + k0 + tig];
                uint32_t b1 = sKb[(nf * 8 + pgrp) * 36 + k0 + tig + 4];
                mma_tf32(sc[nf], a0, a1, a2, a3, b0, b1);
            }
        }

        // ---- bias + exp + PV per 8-sample slice; P stays in registers
#pragma unroll
        for (int nf = 0; nf < 8; nf++) {
            const int kb = nf * 8;
            float2 pA = *(const float2*)&sPb[2 * (kb + tig)];
            float2 pB = *(const float2*)&sPb[2 * (kb + tig + 4)];
            float pb0 = 15.5f * pA.x, pb1 = 15.5f * pA.y;
            float pb2 = 15.5f * pB.x, pb3 = 15.5f * pB.y;
            float e0 = __expf(fmaf(sc[nf][0], scale, bias_Pb(sRb, cg00 - pb0, cg01 - pb1)));
            float e1 = __expf(fmaf(sc[nf][1], scale, bias_Pb(sRb, cg00 - pb2, cg01 - pb3)));
            float e2 = __expf(fmaf(sc[nf][2], scale, bias_Pb(sRb, cg10 - pb0, cg11 - pb1)));
            float e3 = __expf(fmaf(sc[nf][3], scale, bias_Pb(sRb, cg10 - pb2, cg11 - pb3)));
            L0 += e0 + e1;
            L1 += e2 + e3;
            uint32_t a0 = cvt_tf32(e0);
            uint32_t a1 = cvt_tf32(e2);
            uint32_t a2 = cvt_tf32(e1);
            uint32_t a3 = cvt_tf32(e3);
#pragma unroll
            for (int vf = 0; vf < 4; vf++) {
                uint32_t b0 = sVb[(kb + tig) * 36 + vf * 8 + grp];
                uint32_t b1 = sVb[(kb + tig + 4) * 36 + vf * 8 + grp];
                mma_tf32(accv[vf], a0, a1, a2, a3, b0, b1);
            }
        }
    }

    L0 += __shfl_xor_sync(0xffffffffu, L0, 1);
    L0 += __shfl_xor_sync(0xffffffffu, L0, 2);
    L1 += __shfl_xor_sync(0xffffffffu, L1, 1);
    L1 += __shfl_xor_sync(0xffffffffu, L1, 2);
    const float rL0 = 1.f / L0;
    const float rL1 = 1.f / L1;

#pragma unroll
    for (int vf = 0; vf < 4; vf++) {
        int ch = h * 32 + vf * 8 + 2 * tig;
        int base = (b * 256 + ch) * 1024 + mg0;
        out[base]            = accv[vf][0] * rL0;
        out[base + 1024]     = accv[vf][1] * rL0;
        out[base + 8]        = accv[vf][2] * rL1;
        out[base + 1024 + 8] = accv[vf][3] * rL1;
    }
}

// ---------------- launch ----------------
extern "C" void kernel_launch(void* const* d_in, const int* in_sizes, int n_in,
                              void* d_out, int out_size)
{
    const float* x        = (const float*)d_in[0];
    const float* wq       = (const float*)d_in[1];
    const float* bq       = (const float*)d_in[2];
    const float* w_off_dw = (const float*)d_in[3];
    const float* b_off_dw = (const float*)d_in[4];
    const float* ln_g     = (const float*)d_in[5];
    const float* ln_b     = (const float*)d_in[6];
    const float* w_off_pj = (const float*)d_in[7];
    const float* wk       = (const float*)d_in[8];
    const float* bk       = (const float*)d_in[9];
    const float* wv       = (const float*)d_in[10];
    const float* bv       = (const float*)d_in[11];
    const float* wo       = (const float*)d_in[12];
    const float* bo       = (const float*)d_in[13];
    const float* rpe      = (const float*)d_in[14];
    float* out = (float*)d_out;

    float *qb, *xsb, *kb, *vb, *ob, *posb;
    cudaGetSymbolAddress((void**)&qb,   g_q);
    cudaGetSymbolAddress((void**)&xsb,  g_xs);
    cudaGetSymbolAddress((void**)&kb,   g_k);
    cudaGetSymbolAddress((void**)&vb,   g_v);
    cudaGetSymbolAddress((void**)&ob,   g_o);
    cudaGetSymbolAddress((void**)&posb, g_pos);

    const int attn_smem = 72704;
    cudaFuncSetAttribute(attn_mma, cudaFuncAttributeMaxDynamicSharedMemorySize, attn_smem);
    const int gem_smem = 55296;
    cudaFuncSetAttribute(gemm_q_tf32, cudaFuncAttributeMaxDynamicSharedMemorySize, gem_smem);
    cudaFuncSetAttribute(gemm_kv_tf32, cudaFuncAttributeMaxDynamicSharedMemorySize, gem_smem);
    const int off_smem = 163840;
    cudaFuncSetAttribute(offset_kernel, cudaFuncAttributeMaxDynamicSharedMemorySize, off_smem);

    gemm_q_tf32<<<dim3(16, 2, 4), 256, gem_smem>>>(wq, x, bq, qb);
    offset_kernel<<<64, 256, off_smem>>>(qb, w_off_dw, b_off_dw, ln_g, ln_b, w_off_pj,
                                         posb, out + 1048576, out + 1048576 + 32768);
    sample_kernel<<<512, 256>>>(x, posb, xsb);
    gemm_kv_tf32<<<dim3(16, 4, 4), 256, gem_smem>>>(wk, bk, kb, wv, bv, vb, xsb);
    attn_mma<<<dim3(8, 32), 256, attn_smem>>>(qb, kb, vb, rpe, posb, ob);
    gemm_q_tf32<<<dim3(16, 2, 4), 256, gem_smem>>>(wo, ob, bo, out);
}